// round 10
// baseline (speedup 1.0000x reference)
#include <cuda_runtime.h>
#include <cstdint>

// ============================================================
// LIIF_3d via IMMA (mma.sync m16n8k32 s8, s32 accum), exact 3-split fixed point:
//   z*Sa*Sw = 2^14 * sum(ah*wh) + 2^7 * sum(ah*wl + al*wh)   [al*wl dropped]
// Fixes vs round 8: signed char everywhere (aarch64 plain char is UNSIGNED ->
// L4 sign-extension bug), __align__(256) weight arrays for 16B cp.async.
// MQ=128 queries/CTA, 512 threads, warp tile 16x64, two M-half passes,
// in-place activation requantization (half rows disjoint). L4 exact fp32 FFMA,
// t column exact fp32 rank-1. fold3 separate kernel.
// ============================================================

typedef signed char s8;

#define HH   256
#define WWI  256
#define QN   65536
#define CIN  64
#define W0F  30.0f
#define MQ   128
#define SA8  592           // A row stride bytes: 576 + 16 pad
#define SB8  80            // B row stride bytes: 64 + 16 pad

#define SM_COORD 0                         // qy[128] qx[128] tv[128] = 1536B
#define SM_AHI   1536
#define SM_ALO   (SM_AHI + MQ * SA8)       // 77312
#define SM_BHI   (SM_ALO + MQ * SA8)       // 153088
#define SM_BLO   (SM_BHI + 256 * SB8)      // 173568
#define SM_TOTAL (SM_BLO + 256 * SB8)      // 194048 (~189.5KB)

// s8-split transposed weights [n][kp]: L0 256x576 (k = ci*9+r9), L1-3 256x256
#define WT8 344064
__device__ __align__(256) s8 g_w8h[WT8];
__device__ __align__(256) s8 g_w8l[WT8];
__device__ float g_pat[2 * QN * 27];

static __device__ __forceinline__ uint32_t smem_u32(const void* p) {
    uint32_t a;
    asm("{ .reg .u64 t; cvta.to.shared.u64 t, %1; cvt.u32.u64 %0, t; }" : "=r"(a) : "l"(p));
    return a;
}

#define LDSM4(r, addr)                                                              \
    asm volatile("ldmatrix.sync.aligned.m8n8.x4.shared.b16 {%0,%1,%2,%3}, [%4];"    \
                 : "=r"((r)[0]), "=r"((r)[1]), "=r"((r)[2]), "=r"((r)[3])           \
                 : "r"(addr) : "memory")

static __device__ __forceinline__ void imma(int* c, const uint32_t* a, const uint32_t* b) {
    asm volatile(
        "mma.sync.aligned.m16n8k32.row.col.s32.s8.s8.s32 "
        "{%0,%1,%2,%3}, {%4,%5,%6,%7}, {%8,%9}, {%0,%1,%2,%3};"
        : "+r"(c[0]), "+r"(c[1]), "+r"(c[2]), "+r"(c[3])
        : "r"(a[0]), "r"(a[1]), "r"(a[2]), "r"(a[3]), "r"(b[0]), "r"(b[1]));
}

static __device__ __forceinline__ void cpasync16(uint32_t dst, const void* src) {
    asm volatile("cp.async.cg.shared.global [%0], [%1], 16;" :: "r"(dst), "l"(src));
}

// quantize v*S to (qh, ql) with q = 128*qh + ql, |qh|<=127, |ql|<=64
static __device__ __forceinline__ void quant15(float v, float S, s8& qh, s8& ql) {
    float q = rintf(v * S);
    q = fminf(fmaxf(q, -16256.f), 16256.f);
    float h = rintf(q * (1.0f / 128.0f));
    qh = (s8)(int)h;
    ql = (s8)(int)(q - 128.0f * h);
}

// ---------------- prep: transpose + s8 split of weights ----------------
__global__ void prep_kernel(const float* __restrict__ w0, const float* __restrict__ w1,
                            const float* __restrict__ w2, const float* __restrict__ w3) {
    int i = blockIdx.x * 256 + threadIdx.x;
    if (i >= WT8) return;
    float v, S;
    if (i < 147456) {                   // L0: [256 n][576 k]
        int n = i / 576, k = i - n * 576;
        v = w0[k * 256 + n];
        S = 16256.0f / (sqrtf(6.0f / 577.0f) / 30.0f);
    } else {
        int j = i - 147456;
        int l = j >> 16, r = j & 65535;
        int n = r >> 8, k = r & 255;
        const float* wp = (l == 0) ? w1 : (l == 1) ? w2 : w3;
        v = wp[k * 256 + n];
        S = 16256.0f / (sqrtf(6.0f / 256.0f) / 30.0f);
    }
    s8 qh, ql;
    quant15(v, S, qh, ql);
    g_w8h[i] = qh;
    g_w8l[i] = ql;
}

// ---------------- fused MLP ----------------
__global__ __launch_bounds__(512, 1)
void mlp_imma(const float* __restrict__ feat, const float* __restrict__ coord,
              const float* __restrict__ w0_raw,
              const float* __restrict__ b0, const float* __restrict__ b1,
              const float* __restrict__ b2, const float* __restrict__ b3,
              const float* __restrict__ w4, const float* __restrict__ b4) {
    extern __shared__ char smem_raw[];
    s8* smem = (s8*)smem_raw;
    const uint32_t sb = smem_u32(smem);
    int*   qy = (int*)(smem + SM_COORD);
    int*   qx = qy + MQ;
    float* tv = (float*)(qx + MQ);

    const int tid  = threadIdx.x;
    const int lane = tid & 31;
    const int w    = tid >> 5;
    const int wm   = w >> 2;           // 0..3  (16-row group within the half)
    const int wn   = w & 3;            // 0..3  (64-col group)
    const int qbase = blockIdx.x * MQ;
    const int bimg  = qbase >> 16;

    if (tid < MQ) {
        int qg = qbase + tid;
        int q  = qg & (QN - 1);
        const float* cp = coord + (bimg * QN + q) * 3;
        float cy = cp[0], cx = cp[1];
        const float e = 1e-6f;
        cy = fminf(fmaxf(cy, -1.0f + e), 1.0f - e);
        cx = fminf(fmaxf(cx, -1.0f + e), 1.0f - e);
        int iy = (int)rintf((cy + 1.0f) * (HH * 0.5f) - 0.5f);
        int ix = (int)rintf((cx + 1.0f) * (WWI * 0.5f) - 0.5f);
        qy[tid] = min(max(iy, 0), HH - 1);
        qx[tid] = min(max(ix, 0), WWI - 1);
        tv[tid] = cp[2];
    }
    __syncthreads();

    // ---- gather all 576 L0 columns, quantized (scale 16256/6, clamp ±6) ----
    {
        const float SA0 = 16256.0f / 6.0f;
        for (int idx = tid; idx < MQ * 576; idx += 512) {
            int q = idx & (MQ - 1);
            int j = idx >> 7;                  // 0..575 : j = ci*9 + r9
            int ci = j / 9, r9 = j - ci * 9;
            int di = r9 / 3, dj = r9 - di * 3;
            int yy = qy[q] + di - 1, xx = qx[q] + dj - 1;
            float v = (yy >= 0 && yy < HH && xx >= 0 && xx < WWI)
                ? __ldg(feat + ((bimg * CIN + ci) * HH + yy) * WWI + xx) : 0.0f;
            s8 qh, ql;
            quant15(v, SA0, qh, ql);
            smem[SM_AHI + q * SA8 + j] = qh;
            smem[SM_ALO + q * SA8 + j] = ql;
        }
    }

    const float* Bias[4] = {b0, b1, b2, b3};
    const int   seg[4] = {0, 147456, 212992, 278528};
    const int   kps[4] = {576, 256, 256, 256};
    const int   nchs[4] = {9, 4, 4, 4};
    const float bound0 = sqrtf(6.0f / 577.0f) / 30.0f;
    const float bound1 = sqrtf(6.0f / 256.0f) / 30.0f;
    const float inv0 = 6.0f * bound0 / (16256.0f * 16256.0f);
    const float inv1 = bound1 / (16256.0f * 16256.0f);

    for (int l = 0; l < 4; l++) {
        const int kp  = kps[l];
        const int nch = nchs[l];
        const float invS = (l == 0) ? inv0 : inv1;
        const float* bp = Bias[l];

        for (int half = 0; half < 2; half++) {
            int t1[8][4], t23[8][4];
            #pragma unroll
            for (int g = 0; g < 8; g++)
                #pragma unroll
                for (int i = 0; i < 4; i++) { t1[g][i] = 0; t23[g][i] = 0; }

            const int arow = half * 64 + wm * 16 + (lane & 15);
            const uint32_t aHi = sb + SM_AHI + (uint32_t)(arow * SA8 + ((lane >> 4) << 4));
            const uint32_t aLo = sb + SM_ALO + (uint32_t)(arow * SA8 + ((lane >> 4) << 4));
            const int brow = wn * 64 + (lane & 15);
            const uint32_t bHi0 = sb + SM_BHI + (uint32_t)(brow * SB8 + ((lane >> 4) << 4));
            const uint32_t bLo0 = sb + SM_BLO + (uint32_t)(brow * SB8 + ((lane >> 4) << 4));

            for (int c = 0; c < nch; c++) {
                const int kg = c * 64;
                __syncthreads();                   // B buffer free
                {
                    const s8* srcH = g_w8h + seg[l] + kg;
                    const s8* srcL = g_w8l + seg[l] + kg;
                    #pragma unroll
                    for (int p = 0; p < 2; p++) {
                        int idx = tid + p * 512;            // 0..1023
                        int n = idx >> 2, u = idx & 3;
                        cpasync16(sb + SM_BHI + (uint32_t)(n * SB8 + u * 16),
                                  srcH + n * kp + u * 16);
                        cpasync16(sb + SM_BLO + (uint32_t)(n * SB8 + u * 16),
                                  srcL + n * kp + u * 16);
                    }
                    asm volatile("cp.async.commit_group;");
                    asm volatile("cp.async.wait_group 0;" ::: "memory");
                }
                __syncthreads();                   // B visible to all

                #pragma unroll
                for (int ks = 0; ks < 2; ks++) {
                    const uint32_t ka = (uint32_t)(kg + ks * 32);
                    uint32_t Ah[4], Al[4];
                    LDSM4(Ah, aHi + ka);
                    LDSM4(Al, aLo + ka);
                    uint32_t Bh[16], Bl[16];
                    #pragma unroll
                    for (int p = 0; p < 4; p++) {    // p covers n-groups 2p, 2p+1
                        uint32_t r[4];
                        LDSM4(r, bHi0 + (uint32_t)(p * 16 * SB8 + ks * 32));
                        Bh[4 * p + 0] = r[0]; Bh[4 * p + 1] = r[2];   // group 2p
                        Bh[4 * p + 2] = r[1]; Bh[4 * p + 3] = r[3];   // group 2p+1
                    }
                    #pragma unroll
                    for (int g = 0; g < 8; g++)
                        imma(t1[g], Ah, Bh + 2 * g);
                    #pragma unroll
                    for (int g = 0; g < 8; g++)
                        imma(t23[g], Al, Bh + 2 * g);
                    #pragma unroll
                    for (int p = 0; p < 4; p++) {
                        uint32_t r[4];
                        LDSM4(r, bLo0 + (uint32_t)(p * 16 * SB8 + ks * 32));
                        Bl[4 * p + 0] = r[0]; Bl[4 * p + 1] = r[2];
                        Bl[4 * p + 2] = r[1]; Bl[4 * p + 3] = r[3];
                    }
                    #pragma unroll
                    for (int g = 0; g < 8; g++)
                        imma(t23[g], Ah, Bl + 2 * g);
                }
            }

            // ---- epilogue for this half (warp-local rows; no barrier needed) ----
            {
                const int r0 = half * 64 + wm * 16 + (lane >> 2);
                const int r1 = r0 + 8;
                const float tv0 = tv[r0], tv1 = tv[r1];
                #pragma unroll
                for (int g = 0; g < 8; g++) {
                    int col = wn * 64 + g * 8 + 2 * (lane & 3);
                    float2 bb = *(const float2*)(bp + col);
                    float z0 = ((float)t1[g][0] * 16384.f + (float)t23[g][0] * 128.f) * invS;
                    float z1 = ((float)t1[g][1] * 16384.f + (float)t23[g][1] * 128.f) * invS;
                    float z2 = ((float)t1[g][2] * 16384.f + (float)t23[g][2] * 128.f) * invS;
                    float z3 = ((float)t1[g][3] * 16384.f + (float)t23[g][3] * 128.f) * invS;
                    if (l == 0) {   // exact rank-1 t-term
                        float wa = __ldg(w0_raw + 576 * 256 + col);
                        float wb = __ldg(w0_raw + 576 * 256 + col + 1);
                        z0 = fmaf(tv0, wa, z0); z1 = fmaf(tv0, wb, z1);
                        z2 = fmaf(tv1, wa, z2); z3 = fmaf(tv1, wb, z3);
                    }
                    float v0 = __sinf(W0F * (z0 + bb.x));
                    float v1 = __sinf(W0F * (z1 + bb.y));
                    float v2 = __sinf(W0F * (z2 + bb.x));
                    float v3 = __sinf(W0F * (z3 + bb.y));
                    s8 h0, l0, h1, l1, h2, l2, h3, l3;
                    quant15(v0, 16256.f, h0, l0);
                    quant15(v1, 16256.f, h1, l1);
                    quant15(v2, 16256.f, h2, l2);
                    quant15(v3, 16256.f, h3, l3);
                    // pack pairs (little-endian byte order)
                    uint16_t ph0 = (uint16_t)((uint8_t)h0 | ((uint16_t)(uint8_t)h1 << 8));
                    uint16_t pl0 = (uint16_t)((uint8_t)l0 | ((uint16_t)(uint8_t)l1 << 8));
                    uint16_t ph1 = (uint16_t)((uint8_t)h2 | ((uint16_t)(uint8_t)h3 << 8));
                    uint16_t pl1 = (uint16_t)((uint8_t)l2 | ((uint16_t)(uint8_t)l3 << 8));
                    *(uint16_t*)(smem + SM_AHI + r0 * SA8 + col) = ph0;
                    *(uint16_t*)(smem + SM_ALO + r0 * SA8 + col) = pl0;
                    *(uint16_t*)(smem + SM_AHI + r1 * SA8 + col) = ph1;
                    *(uint16_t*)(smem + SM_ALO + r1 * SA8 + col) = pl1;
                }
            }
        }
    }

    // ---------------- L4: 256 -> 27 in fp32 FFMA (sign-extended reads!) ----------------
    {
        __syncthreads();                          // L3 epilogues visible; B area free
        float* ws = (float*)(smem + SM_BHI);      // 256*27 floats = 27648B
        for (int i = tid; i < 256 * 27; i += 512) ws[i] = __ldg(w4 + i);
        __syncthreads();

        const int q  = tid >> 2;                  // 0..127
        const int cj = tid & 3;
        const s8* Ahp = smem + SM_AHI + q * SA8;
        const s8* Alp = smem + SM_ALO + q * SA8;
        const float invA = 1.0f / 16256.0f;
        float a4[7];
        #pragma unroll
        for (int j = 0; j < 7; j++) a4[j] = 0.0f;
        #pragma unroll 4
        for (int k = 0; k < 256; k++) {
            float a = ((float)(128 * (int)Ahp[k] + (int)Alp[k])) * invA;
            #pragma unroll
            for (int j = 0; j < 7; j++) {
                int c = cj + 4 * j;
                if (c < 27) a4[j] = fmaf(a, ws[k * 27 + c], a4[j]);
            }
        }
        const int qg = qbase + q;
        #pragma unroll
        for (int j = 0; j < 7; j++) {
            int c = cj + 4 * j;
            if (c < 27) g_pat[qg * 27 + c] = a4[j] + __ldg(b4 + c);
        }
    }
}

// ---------------- fold3 ----------------
__global__ void fold_kernel(float* __restrict__ out) {
    int idx = blockIdx.x * blockDim.x + threadIdx.x;
    if (idx >= 2 * QN) return;
    int b = idx >> 16;
    int p = idx & (QN - 1);
    int y = p >> 8, x = p & 255;
    float s0 = 0.f, s1 = 0.f, s2 = 0.f;
    #pragma unroll
    for (int i = 0; i < 3; i++) {
        int yy = y + 1 - i;
        if (yy < 0 || yy >= HH) continue;
        #pragma unroll
        for (int j = 0; j < 3; j++) {
            int xx = x + 1 - j;
            if (xx < 0 || xx >= WWI) continue;
            const float* pp = g_pat + (b * QN + yy * WWI + xx) * 27 + i * 3 + j;
            s0 += pp[0];
            s1 += pp[9];
            s2 += pp[18];
        }
    }
    out[(b * 3 + 0) * QN + p] = s0;
    out[(b * 3 + 1) * QN + p] = s1;
    out[(b * 3 + 2) * QN + p] = s2;
}

extern "C" void kernel_launch(void* const* d_in, const int* in_sizes, int n_in,
                              void* d_out, int out_size) {
    const float* feat  = (const float*)d_in[0];
    const float* coord = (const float*)d_in[1];
    const float* w0 = (const float*)d_in[2];
    const float* b0 = (const float*)d_in[3];
    const float* w1 = (const float*)d_in[4];
    const float* b1 = (const float*)d_in[5];
    const float* w2 = (const float*)d_in[6];
    const float* b2 = (const float*)d_in[7];
    const float* w3 = (const float*)d_in[8];
    const float* b3 = (const float*)d_in[9];
    const float* w4 = (const float*)d_in[10];
    const float* b4 = (const float*)d_in[11];
    float* out = (float*)d_out;

    prep_kernel<<<(WT8 + 255) / 256, 256>>>(w0, w1, w2, w3);

    cudaFuncSetAttribute(mlp_imma, cudaFuncAttributeMaxDynamicSharedMemorySize, SM_TOTAL);
    mlp_imma<<<(2 * QN) / MQ, 512, SM_TOTAL>>>(feat, coord, w0, b0, b1, b2, b3, w4, b4);

    fold_kernel<<<(2 * QN + 255) / 256, 256>>>(out);
}

// round 11
// speedup vs baseline: 2.1607x; 2.1607x over previous
#include <cuda_runtime.h>
#include <cuda_fp16.h>
#include <cstdint>

// ============================================================
// LIIF_3d via HMMA hi/lo 3-split, ALL f32-acc (corr-f16 machinery removed —
// measured same MMA rate, so the per-chunk flush was pure overhead):
//   z = sum(ah*bh) + sum(al*bh) + sum(ah*bl), each m16n8k16 f32-acc.
// MQ=128 queries/CTA, 512 threads, warp tile 32x64, K-chunk 64.
// L0 K=576 (t column = exact fp32 rank-1 in epilogue).
// L4 (256->27) exact fp32 FFMA (half2-vectorized A reads). fold3 separate.
// ============================================================

#define HH   256
#define WWI  256
#define QN   65536
#define CIN  64
#define W0F  30.0f
#define MQ   128
#define SA   264           // A row stride (halfs): 256 + 8 pad
#define SB   72            // B row stride (halfs): 64 + 8 pad

#define SM_COORD 0                          // qy[128] qx[128] tv[128]
#define SM_AHI   2048
#define SM_ALO   (SM_AHI + MQ * SA * 2)     // 69632
#define SM_BHI   (SM_ALO + MQ * SA * 2)     // 137216
#define SM_BLO   (SM_BHI + 256 * SB * 2)    // 174080
#define SM_TOTAL (SM_BLO + 256 * SB * 2)    // 210944

// transposed split weights [n][kp]: L0 256x640 (cols>=577 zero), L1-3 256x256
#define WT_ELEMS 360448
__device__ __align__(256) __half g_wt_hi[WT_ELEMS];
__device__ __align__(256) __half g_wt_lo[WT_ELEMS];
__device__ float  g_pat[2 * QN * 27];

static __device__ __forceinline__ uint32_t smem_u32(const void* p) {
    uint32_t a;
    asm("{ .reg .u64 t; cvta.to.shared.u64 t, %1; cvt.u32.u64 %0, t; }" : "=r"(a) : "l"(p));
    return a;
}

#define LDSM4(r, addr)                                                              \
    asm volatile("ldmatrix.sync.aligned.m8n8.x4.shared.b16 {%0,%1,%2,%3}, [%4];"    \
                 : "=r"((r)[0]), "=r"((r)[1]), "=r"((r)[2]), "=r"((r)[3])           \
                 : "r"(addr) : "memory")

static __device__ __forceinline__ void mma_f32(float* c, const uint32_t* a, const uint32_t* b) {
    asm volatile(
        "mma.sync.aligned.m16n8k16.row.col.f32.f16.f16.f32 "
        "{%0,%1,%2,%3}, {%4,%5,%6,%7}, {%8,%9}, {%0,%1,%2,%3};"
        : "+f"(c[0]), "+f"(c[1]), "+f"(c[2]), "+f"(c[3])
        : "r"(a[0]), "r"(a[1]), "r"(a[2]), "r"(a[3]), "r"(b[0]), "r"(b[1]));
}

// ---------------- prep: transpose + hi/lo split ----------------
__global__ void prep_kernel(const float* __restrict__ w0, const float* __restrict__ w1,
                            const float* __restrict__ w2, const float* __restrict__ w3) {
    int i = blockIdx.x * 256 + threadIdx.x;
    if (i >= WT_ELEMS) return;
    float v;
    if (i < 163840) {                 // L0 [256][640]
        int n = i / 640, k = i - n * 640;
        v = (k < 577) ? w0[k * 256 + n] : 0.0f;
    } else if (i < 229376) {
        int j = i - 163840; int n = j >> 8, k = j & 255; v = w1[k * 256 + n];
    } else if (i < 294912) {
        int j = i - 229376; int n = j >> 8, k = j & 255; v = w2[k * 256 + n];
    } else {
        int j = i - 294912; int n = j >> 8, k = j & 255; v = w3[k * 256 + n];
    }
    __half h = __float2half_rn(v);
    g_wt_hi[i] = h;
    g_wt_lo[i] = __float2half_rn(v - __half2float(h));
}

// ---------------- fused MLP ----------------
__global__ __launch_bounds__(512, 1)
void mlp_hmma(const float* __restrict__ feat, const float* __restrict__ coord,
              const float* __restrict__ w0_raw,
              const float* __restrict__ b0, const float* __restrict__ b1,
              const float* __restrict__ b2, const float* __restrict__ b3,
              const float* __restrict__ w4, const float* __restrict__ b4) {
    extern __shared__ char smem[];
    const uint32_t sb = smem_u32(smem);
    int*   qy = (int*)(smem + SM_COORD);
    int*   qx = qy + MQ;
    float* tv = (float*)(qx + MQ);

    const int tid  = threadIdx.x;
    const int lane = tid & 31;
    const int w    = tid >> 5;
    const int wm   = w >> 2;           // 0..3 (M groups of 32 rows)
    const int wn   = w & 3;            // 0..3 (N groups of 64 cols)
    const int qbase = blockIdx.x * MQ;
    const int bimg  = qbase >> 16;

    if (tid < MQ) {
        int qg = qbase + tid;
        int q  = qg & (QN - 1);
        const float* cp = coord + (bimg * QN + q) * 3;
        float cy = cp[0], cx = cp[1];
        const float e = 1e-6f;
        cy = fminf(fmaxf(cy, -1.0f + e), 1.0f - e);
        cx = fminf(fmaxf(cx, -1.0f + e), 1.0f - e);
        int iy = (int)rintf((cy + 1.0f) * (HH * 0.5f) - 0.5f);
        int ix = (int)rintf((cx + 1.0f) * (WWI * 0.5f) - 0.5f);
        qy[tid] = min(max(iy, 0), HH - 1);
        qx[tid] = min(max(ix, 0), WWI - 1);
        tv[tid] = cp[2];
    }
    __syncthreads();

    const float* Bias[4] = {b0, b1, b2, b3};
    const int seg[4] = {0, 163840, 229376, 294912};
    const int kps[4] = {640, 256, 256, 256};

    const int rowbase = wm * 32;
    const uint32_t a_off = (uint32_t)(((rowbase + (lane & 15)) * SA + ((lane >> 4) << 3)) * 2);
    const uint32_t aHi = sb + SM_AHI + a_off;
    const uint32_t aLo = sb + SM_ALO + a_off;
    const uint32_t b_off = (uint32_t)(((wn * 64 + ((lane >> 4) << 3) + (lane & 7)) * SB +
                                      ((lane >> 3) & 1) * 8) * 2);
    const uint32_t bHi = sb + SM_BHI + b_off;
    const uint32_t bLo = sb + SM_BLO + b_off;

    float acc[2][8][4];

    for (int l = 0; l < 4; l++) {
        #pragma unroll
        for (int mt = 0; mt < 2; mt++)
            #pragma unroll
            for (int nt = 0; nt < 8; nt++)
                #pragma unroll
                for (int i = 0; i < 4; i++) acc[mt][nt][i] = 0.0f;

        const int kp = kps[l];
        const int nstages = (l == 0) ? 3 : 1;

        for (int s = 0; s < nstages; s++) {
            const int klen = (l == 0) ? ((s < 2) ? 256 : 64) : 256;
            __syncthreads();                        // A region free
            if (l == 0) {
                for (int idx = tid; idx < MQ * klen; idx += 512) {
                    int q = idx & (MQ - 1);
                    int j = idx >> 7;
                    int k = s * 256 + j;            // always < 576
                    int ci = k / 9, r9 = k - ci * 9;
                    int di = r9 / 3, dj = r9 - di * 3;
                    int yy = qy[q] + di - 1, xx = qx[q] + dj - 1;
                    float v = (yy >= 0 && yy < HH && xx >= 0 && xx < WWI)
                        ? __ldg(feat + ((bimg * CIN + ci) * HH + yy) * WWI + xx) : 0.0f;
                    __half h  = __float2half_rn(v);
                    __half lo = __float2half_rn(v - __half2float(h));
                    uint32_t off = (uint32_t)((q * SA + j) * 2);
                    *(__half*)(smem + SM_AHI + off) = h;
                    *(__half*)(smem + SM_ALO + off) = lo;
                }
            }
            const int nch = klen >> 6;
            for (int c = 0; c < nch; c++) {
                const int kg = s * 256 + c * 64;
                __syncthreads();                    // B buffer free (and gather visible)
                for (int idx = tid; idx < 256 * 8; idx += 512) {
                    int n = idx >> 3, u = idx & 7;
                    uint32_t soff = (uint32_t)((n * SB + u * 8) * 2);
                    const __half* ph = g_wt_hi + seg[l] + n * kp + kg + u * 8;
                    const __half* pl = g_wt_lo + seg[l] + n * kp + kg + u * 8;
                    *(uint4*)(smem + SM_BHI + soff) = *(const uint4*)ph;
                    *(uint4*)(smem + SM_BLO + soff) = *(const uint4*)pl;
                }
                __syncthreads();
                #pragma unroll
                for (int ks = 0; ks < 4; ks++) {
                    const uint32_t ca2 = (uint32_t)((c * 64 + ks * 16) * 2);
                    uint32_t Ah[8], Al[8];
                    LDSM4(Ah,     aHi + ca2);
                    LDSM4(Ah + 4, aHi + ca2 + 16 * SA * 2);
                    LDSM4(Al,     aLo + ca2);
                    LDSM4(Al + 4, aLo + ca2 + 16 * SA * 2);
                    {
                        uint32_t Bh[16];
                        #pragma unroll
                        for (int p = 0; p < 4; p++)
                            LDSM4(Bh + 4 * p, bHi + (uint32_t)(p * 16 * SB * 2 + ks * 32));
                        #pragma unroll
                        for (int mt = 0; mt < 2; mt++)
                            #pragma unroll
                            for (int nt = 0; nt < 8; nt++)
                                mma_f32(acc[mt][nt], Ah + 4 * mt, Bh + 2 * nt);
                        #pragma unroll
                        for (int mt = 0; mt < 2; mt++)
                            #pragma unroll
                            for (int nt = 0; nt < 8; nt++)
                                mma_f32(acc[mt][nt], Al + 4 * mt, Bh + 2 * nt);
                    }
                    {
                        uint32_t Bl[16];
                        #pragma unroll
                        for (int p = 0; p < 4; p++)
                            LDSM4(Bl + 4 * p, bLo + (uint32_t)(p * 16 * SB * 2 + ks * 32));
                        #pragma unroll
                        for (int mt = 0; mt < 2; mt++)
                            #pragma unroll
                            for (int nt = 0; nt < 8; nt++)
                                mma_f32(acc[mt][nt], Ah + 4 * mt, Bl + 2 * nt);
                    }
                }
            }
        }

        __syncthreads();   // all warps done reading A before epilogue overwrites it
        {
            const float* bp = Bias[l];
            const int trow  = rowbase + (lane >> 2);
            const int tcol0 = wn * 64 + 2 * (lane & 3);
            #pragma unroll
            for (int mt = 0; mt < 2; mt++) {
                const int r0 = trow + mt * 16;
                const int r1 = r0 + 8;
                const float tv0 = tv[r0], tv1 = tv[r1];
                #pragma unroll
                for (int nt = 0; nt < 8; nt++) {
                    int col = tcol0 + nt * 8;
                    float2 bb = *(const float2*)(bp + col);
                    float a0 = acc[mt][nt][0], a1 = acc[mt][nt][1];
                    float a2 = acc[mt][nt][2], a3 = acc[mt][nt][3];
                    if (l == 0) {   // exact rank-1 t-term: tv * w0[576,:]
                        float wa = __ldg(w0_raw + 576 * 256 + col);
                        float wb = __ldg(w0_raw + 576 * 256 + col + 1);
                        a0 = fmaf(tv0, wa, a0); a1 = fmaf(tv0, wb, a1);
                        a2 = fmaf(tv1, wa, a2); a3 = fmaf(tv1, wb, a3);
                    }
                    float v00 = __sinf(W0F * (a0 + bb.x));
                    float v01 = __sinf(W0F * (a1 + bb.y));
                    float v10 = __sinf(W0F * (a2 + bb.x));
                    float v11 = __sinf(W0F * (a3 + bb.y));
                    __half h00 = __float2half_rn(v00), h01 = __float2half_rn(v01);
                    __half h10 = __float2half_rn(v10), h11 = __float2half_rn(v11);
                    __half l00 = __float2half_rn(v00 - __half2float(h00));
                    __half l01 = __float2half_rn(v01 - __half2float(h01));
                    __half l10 = __float2half_rn(v10 - __half2float(h10));
                    __half l11 = __float2half_rn(v11 - __half2float(h11));
                    uint32_t o0 = (uint32_t)((r0 * SA + col) * 2);
                    uint32_t o1 = (uint32_t)((r1 * SA + col) * 2);
                    *(__half2*)(smem + SM_AHI + o0) = __halves2half2(h00, h01);
                    *(__half2*)(smem + SM_ALO + o0) = __halves2half2(l00, l01);
                    *(__half2*)(smem + SM_AHI + o1) = __halves2half2(h10, h11);
                    *(__half2*)(smem + SM_ALO + o1) = __halves2half2(l10, l11);
                }
            }
        }
    }

    // ---------------- L4: 256 -> 27 in fp32 FFMA (half2 A reads) ----------------
    {
        __syncthreads();                          // L3 epilogues visible; B area free
        float* ws = (float*)(smem + SM_BHI);      // 256*27 floats = 27648B
        for (int i = tid; i < 256 * 27; i += 512) ws[i] = __ldg(w4 + i);
        __syncthreads();

        const int q  = tid >> 2;                  // 0..127
        const int cj = tid & 3;
        const __half2* Ahp = (const __half2*)((const __half*)(smem + SM_AHI) + q * SA);
        const __half2* Alp = (const __half2*)((const __half*)(smem + SM_ALO) + q * SA);
        float a4[7];
        #pragma unroll
        for (int j = 0; j < 7; j++) a4[j] = 0.0f;
        #pragma unroll 4
        for (int k2 = 0; k2 < 128; k2++) {
            float2 fh = __half22float2(Ahp[k2]);
            float2 fl = __half22float2(Alp[k2]);
            float aE = fh.x + fl.x;
            float aO = fh.y + fl.y;
            const float* wE = ws + (2 * k2) * 27;
            const float* wO = wE + 27;
            #pragma unroll
            for (int j = 0; j < 7; j++) {
                int c = cj + 4 * j;
                if (c < 27) {
                    a4[j] = fmaf(aE, wE[c], a4[j]);
                    a4[j] = fmaf(aO, wO[c], a4[j]);
                }
            }
        }
        const int qg = qbase + q;
        #pragma unroll
        for (int j = 0; j < 7; j++) {
            int c = cj + 4 * j;
            if (c < 27) g_pat[qg * 27 + c] = a4[j] + __ldg(b4 + c);
        }
    }
}

// ---------------- fold3 ----------------
__global__ void fold_kernel(float* __restrict__ out) {
    int idx = blockIdx.x * blockDim.x + threadIdx.x;
    if (idx >= 2 * QN) return;
    int b = idx >> 16;
    int p = idx & (QN - 1);
    int y = p >> 8, x = p & 255;
    float s0 = 0.f, s1 = 0.f, s2 = 0.f;
    #pragma unroll
    for (int i = 0; i < 3; i++) {
        int yy = y + 1 - i;
        if (yy < 0 || yy >= HH) continue;
        #pragma unroll
        for (int j = 0; j < 3; j++) {
            int xx = x + 1 - j;
            if (xx < 0 || xx >= WWI) continue;
            const float* pp = g_pat + (b * QN + yy * WWI + xx) * 27 + i * 3 + j;
            s0 += pp[0];
            s1 += pp[9];
            s2 += pp[18];
        }
    }
    out[(b * 3 + 0) * QN + p] = s0;
    out[(b * 3 + 1) * QN + p] = s1;
    out[(b * 3 + 2) * QN + p] = s2;
}

extern "C" void kernel_launch(void* const* d_in, const int* in_sizes, int n_in,
                              void* d_out, int out_size) {
    const float* feat  = (const float*)d_in[0];
    const float* coord = (const float*)d_in[1];
    const float* w0 = (const float*)d_in[2];
    const float* b0 = (const float*)d_in[3];
    const float* w1 = (const float*)d_in[4];
    const float* b1 = (const float*)d_in[5];
    const float* w2 = (const float*)d_in[6];
    const float* b2 = (const float*)d_in[7];
    const float* w3 = (const float*)d_in[8];
    const float* b3 = (const float*)d_in[9];
    const float* w4 = (const float*)d_in[10];
    const float* b4 = (const float*)d_in[11];
    float* out = (float*)d_out;

    prep_kernel<<<(WT_ELEMS + 255) / 256, 256>>>(w0, w1, w2, w3);

    cudaFuncSetAttribute(mlp_hmma, cudaFuncAttributeMaxDynamicSharedMemorySize, SM_TOTAL);
    mlp_hmma<<<(2 * QN) / MQ, 512, SM_TOTAL>>>(feat, coord, w0, b0, b1, b2, b3, w4, b4);

    fold_kernel<<<(2 * QN + 255) / 256, 256>>>(out);
}

// round 12
// speedup vs baseline: 2.2660x; 1.0487x over previous
#include <cuda_runtime.h>
#include <cuda_fp16.h>
#include <cstdint>

// ============================================================
// LIIF_3d via HMMA hi/lo 3-split, all f32-acc.
// NEW vs round 11: k32 cp.async double-buffered B staging with ONE barrier
// per chunk (wait_group -> barrier -> issue-next -> MMA), so L2 latency is
// fully hidden; stage-0 prefetch overlaps the L0 gather.
// MQ=128 queries/CTA, 512 threads, warp tile 32x64.
// L0 K=576 (t column = exact fp32 rank-1). L4 exact fp32 FFMA. fold3 separate.
// ============================================================

#define HH   256
#define WWI  256
#define QN   65536
#define CIN  64
#define W0F  30.0f
#define MQ   128
#define SA   264           // A row stride (halfs): 256 + 8 pad
#define SB   40            // B row stride (halfs): 32 + 8 pad (80B rows)

#define SM_COORD 0                      // qy[128] qx[128] tv[128]
#define SM_AHI   2048
#define SM_ALO   69632                  // + 128*264*2 = 67584
#define SM_BH0   137216                 // each B plane: 256*80 = 20480
#define SM_BL0   157696
#define SM_BH1   178176
#define SM_BL1   198656
#define SM_TOTAL 219136                 // 214 KB

// transposed split weights [n][kp]: L0 256x640 (cols>=577 zero), L1-3 256x256
#define WT_ELEMS 360448
__device__ __align__(256) __half g_wt_hi[WT_ELEMS];
__device__ __align__(256) __half g_wt_lo[WT_ELEMS];
__device__ float  g_pat[2 * QN * 27];

static __device__ __forceinline__ uint32_t smem_u32(const void* p) {
    uint32_t a;
    asm("{ .reg .u64 t; cvta.to.shared.u64 t, %1; cvt.u32.u64 %0, t; }" : "=r"(a) : "l"(p));
    return a;
}

#define LDSM4(r, addr)                                                              \
    asm volatile("ldmatrix.sync.aligned.m8n8.x4.shared.b16 {%0,%1,%2,%3}, [%4];"    \
                 : "=r"((r)[0]), "=r"((r)[1]), "=r"((r)[2]), "=r"((r)[3])           \
                 : "r"(addr) : "memory")

#define CP16(dst, src) asm volatile("cp.async.cg.shared.global [%0], [%1], 16;" :: "r"(dst), "l"(src))
#define CP_COMMIT()    asm volatile("cp.async.commit_group;" ::: "memory")
#define CP_WAIT0()     asm volatile("cp.async.wait_group 0;" ::: "memory")

static __device__ __forceinline__ void mma_f32(float* c, const uint32_t* a, const uint32_t* b) {
    asm volatile(
        "mma.sync.aligned.m16n8k16.row.col.f32.f16.f16.f32 "
        "{%0,%1,%2,%3}, {%4,%5,%6,%7}, {%8,%9}, {%0,%1,%2,%3};"
        : "+f"(c[0]), "+f"(c[1]), "+f"(c[2]), "+f"(c[3])
        : "r"(a[0]), "r"(a[1]), "r"(a[2]), "r"(a[3]), "r"(b[0]), "r"(b[1]));
}

// ---------------- prep: transpose + hi/lo split ----------------
__global__ void prep_kernel(const float* __restrict__ w0, const float* __restrict__ w1,
                            const float* __restrict__ w2, const float* __restrict__ w3) {
    int i = blockIdx.x * 256 + threadIdx.x;
    if (i >= WT_ELEMS) return;
    float v;
    if (i < 163840) {                 // L0 [256][640]
        int n = i / 640, k = i - n * 640;
        v = (k < 577) ? w0[k * 256 + n] : 0.0f;
    } else if (i < 229376) {
        int j = i - 163840; int n = j >> 8, k = j & 255; v = w1[k * 256 + n];
    } else if (i < 294912) {
        int j = i - 229376; int n = j >> 8, k = j & 255; v = w2[k * 256 + n];
    } else {
        int j = i - 294912; int n = j >> 8, k = j & 255; v = w3[k * 256 + n];
    }
    __half h = __float2half_rn(v);
    g_wt_hi[i] = h;
    g_wt_lo[i] = __float2half_rn(v - __half2float(h));
}

// stage one k32 chunk of B (both planes) via cp.async; kg in halfs from layer base
static __device__ __forceinline__ void stage_b(uint32_t bh, uint32_t bl,
                                               const __half* srcH, const __half* srcL,
                                               int kp, int kg, int tid) {
    #pragma unroll
    for (int p = 0; p < 2; p++) {
        int idx = tid + p * 512;              // 0..1023 : n = idx>>2, u = idx&3
        int n = idx >> 2, u = idx & 3;
        CP16(bh + (uint32_t)(n * 80 + u * 16), srcH + n * kp + kg + u * 8);
        CP16(bl + (uint32_t)(n * 80 + u * 16), srcL + n * kp + kg + u * 8);
    }
    CP_COMMIT();
}

// ---------------- fused MLP ----------------
__global__ __launch_bounds__(512, 1)
void mlp_hmma(const float* __restrict__ feat, const float* __restrict__ coord,
              const float* __restrict__ w0_raw,
              const float* __restrict__ b0, const float* __restrict__ b1,
              const float* __restrict__ b2, const float* __restrict__ b3,
              const float* __restrict__ w4, const float* __restrict__ b4) {
    extern __shared__ char smem[];
    const uint32_t sb = smem_u32(smem);
    int*   qy = (int*)(smem + SM_COORD);
    int*   qx = qy + MQ;
    float* tv = (float*)(qx + MQ);

    const int tid  = threadIdx.x;
    const int lane = tid & 31;
    const int w    = tid >> 5;
    const int wm   = w >> 2;           // 0..3 (M groups of 32 rows)
    const int wn   = w & 3;            // 0..3 (N groups of 64 cols)
    const int qbase = blockIdx.x * MQ;
    const int bimg  = qbase >> 16;

    if (tid < MQ) {
        int qg = qbase + tid;
        int q  = qg & (QN - 1);
        const float* cp = coord + (bimg * QN + q) * 3;
        float cy = cp[0], cx = cp[1];
        const float e = 1e-6f;
        cy = fminf(fmaxf(cy, -1.0f + e), 1.0f - e);
        cx = fminf(fmaxf(cx, -1.0f + e), 1.0f - e);
        int iy = (int)rintf((cy + 1.0f) * (HH * 0.5f) - 0.5f);
        int ix = (int)rintf((cx + 1.0f) * (WWI * 0.5f) - 0.5f);
        qy[tid] = min(max(iy, 0), HH - 1);
        qx[tid] = min(max(ix, 0), WWI - 1);
        tv[tid] = cp[2];
    }
    __syncthreads();

    const float* Bias[4] = {b0, b1, b2, b3};
    const int seg[4] = {0, 163840, 229376, 294912};
    const int kps[4] = {640, 256, 256, 256};

    const int rowbase = wm * 32;
    const uint32_t a_off = (uint32_t)(((rowbase + (lane & 15)) * SA + ((lane >> 4) << 3)) * 2);
    const uint32_t aHi = sb + SM_AHI + a_off;
    const uint32_t aLo = sb + SM_ALO + a_off;
    const uint32_t b_off = (uint32_t)(((wn * 64 + ((lane >> 4) << 3) + (lane & 7)) * SB +
                                      ((lane >> 3) & 1) * 8) * 2);
    const uint32_t BHp[2] = {sb + SM_BH0, sb + SM_BH1};
    const uint32_t BLp[2] = {sb + SM_BL0, sb + SM_BL1};

    float acc[2][8][4];

    for (int l = 0; l < 4; l++) {
        #pragma unroll
        for (int mt = 0; mt < 2; mt++)
            #pragma unroll
            for (int nt = 0; nt < 8; nt++)
                #pragma unroll
                for (int i = 0; i < 4; i++) acc[mt][nt][i] = 0.0f;

        const int kp = kps[l];
        const __half* srcH = g_wt_hi + seg[l];
        const __half* srcL = g_wt_lo + seg[l];
        const int nstages = (l == 0) ? 3 : 1;

        for (int s = 0; s < nstages; s++) {
            const int klen = (l == 0) ? ((s < 2) ? 256 : 64) : 256;
            const int nch  = klen >> 5;            // k32 chunks
            __syncthreads();                       // A free; prev B readers done

            // prefetch chunk 0 (overlaps gather below)
            stage_b(BHp[0], BLp[0], srcH, srcL, kp, s * 256, tid);

            if (l == 0) {
                for (int idx = tid; idx < MQ * klen; idx += 512) {
                    int q = idx & (MQ - 1);
                    int j = idx >> 7;
                    int k = s * 256 + j;           // < 576
                    int ci = k / 9, r9 = k - ci * 9;
                    int di = r9 / 3, dj = r9 - di * 3;
                    int yy = qy[q] + di - 1, xx = qx[q] + dj - 1;
                    float v = (yy >= 0 && yy < HH && xx >= 0 && xx < WWI)
                        ? __ldg(feat + ((bimg * CIN + ci) * HH + yy) * WWI + xx) : 0.0f;
                    __half h  = __float2half_rn(v);
                    __half lo = __float2half_rn(v - __half2float(h));
                    uint32_t off = (uint32_t)((q * SA + j) * 2);
                    *(__half*)(smem + SM_AHI + off) = h;
                    *(__half*)(smem + SM_ALO + off) = lo;
                }
            }

            for (int c = 0; c < nch; c++) {
                CP_WAIT0();           // chunk c landed (per-thread)
                __syncthreads();      // publish chunk c; chunk c-1 readers done
                if (c + 1 < nch)      // safe now: buf[(c+1)&1] readers finished
                    stage_b(BHp[(c + 1) & 1], BLp[(c + 1) & 1], srcH, srcL,
                            kp, s * 256 + (c + 1) * 32, tid);

                const uint32_t bHi = BHp[c & 1] + b_off;
                const uint32_t bLo = BLp[c & 1] + b_off;

                #pragma unroll
                for (int ks = 0; ks < 2; ks++) {
                    const uint32_t ca2 = (uint32_t)((c * 32 + ks * 16) * 2);
                    uint32_t Ah[8], Al[8];
                    LDSM4(Ah,     aHi + ca2);
                    LDSM4(Ah + 4, aHi + ca2 + 16 * SA * 2);
                    LDSM4(Al,     aLo + ca2);
                    LDSM4(Al + 4, aLo + ca2 + 16 * SA * 2);
                    {
                        uint32_t Bh[16];
                        #pragma unroll
                        for (int p = 0; p < 4; p++)
                            LDSM4(Bh + 4 * p, bHi + (uint32_t)(p * 16 * SB * 2 + ks * 32));
                        #pragma unroll
                        for (int mt = 0; mt < 2; mt++)
                            #pragma unroll
                            for (int nt = 0; nt < 8; nt++)
                                mma_f32(acc[mt][nt], Ah + 4 * mt, Bh + 2 * nt);
                        #pragma unroll
                        for (int mt = 0; mt < 2; mt++)
                            #pragma unroll
                            for (int nt = 0; nt < 8; nt++)
                                mma_f32(acc[mt][nt], Al + 4 * mt, Bh + 2 * nt);
                    }
                    {
                        uint32_t Bl[16];
                        #pragma unroll
                        for (int p = 0; p < 4; p++)
                            LDSM4(Bl + 4 * p, bLo + (uint32_t)(p * 16 * SB * 2 + ks * 32));
                        #pragma unroll
                        for (int mt = 0; mt < 2; mt++)
                            #pragma unroll
                            for (int nt = 0; nt < 8; nt++)
                                mma_f32(acc[mt][nt], Ah + 4 * mt, Bl + 2 * nt);
                    }
                }
            }
        }

        __syncthreads();   // all warps done reading A before epilogue overwrites it
        {
            const float* bp = Bias[l];
            const int trow  = rowbase + (lane >> 2);
            const int tcol0 = wn * 64 + 2 * (lane & 3);
            #pragma unroll
            for (int mt = 0; mt < 2; mt++) {
                const int r0 = trow + mt * 16;
                const int r1 = r0 + 8;
                const float tv0 = tv[r0], tv1 = tv[r1];
                #pragma unroll
                for (int nt = 0; nt < 8; nt++) {
                    int col = tcol0 + nt * 8;
                    float2 bb = *(const float2*)(bp + col);
                    float a0 = acc[mt][nt][0], a1 = acc[mt][nt][1];
                    float a2 = acc[mt][nt][2], a3 = acc[mt][nt][3];
                    if (l == 0) {   // exact rank-1 t-term: tv * w0[576,:]
                        float wa = __ldg(w0_raw + 576 * 256 + col);
                        float wb = __ldg(w0_raw + 576 * 256 + col + 1);
                        a0 = fmaf(tv0, wa, a0); a1 = fmaf(tv0, wb, a1);
                        a2 = fmaf(tv1, wa, a2); a3 = fmaf(tv1, wb, a3);
                    }
                    float v00 = __sinf(W0F * (a0 + bb.x));
                    float v01 = __sinf(W0F * (a1 + bb.y));
                    float v10 = __sinf(W0F * (a2 + bb.x));
                    float v11 = __sinf(W0F * (a3 + bb.y));
                    __half h00 = __float2half_rn(v00), h01 = __float2half_rn(v01);
                    __half h10 = __float2half_rn(v10), h11 = __float2half_rn(v11);
                    __half l00 = __float2half_rn(v00 - __half2float(h00));
                    __half l01 = __float2half_rn(v01 - __half2float(h01));
                    __half l10 = __float2half_rn(v10 - __half2float(h10));
                    __half l11 = __float2half_rn(v11 - __half2float(h11));
                    uint32_t o0 = (uint32_t)((r0 * SA + col) * 2);
                    uint32_t o1 = (uint32_t)((r1 * SA + col) * 2);
                    *(__half2*)(smem + SM_AHI + o0) = __halves2half2(h00, h01);
                    *(__half2*)(smem + SM_ALO + o0) = __halves2half2(l00, l01);
                    *(__half2*)(smem + SM_AHI + o1) = __halves2half2(h10, h11);
                    *(__half2*)(smem + SM_ALO + o1) = __halves2half2(l10, l11);
                }
            }
        }
    }

    // ---------------- L4: 256 -> 27 in fp32 FFMA (half2 A reads) ----------------
    {
        __syncthreads();                          // L3 epilogues visible; B area free
        float* ws = (float*)(smem + SM_BH0);      // 256*27 floats = 27648B
        for (int i = tid; i < 256 * 27; i += 512) ws[i] = __ldg(w4 + i);
        __syncthreads();

        const int q  = tid >> 2;                  // 0..127
        const int cj = tid & 3;
        const __half2* Ahp = (const __half2*)((const __half*)(smem + SM_AHI) + q * SA);
        const __half2* Alp = (const __half2*)((const __half*)(smem + SM_ALO) + q * SA);
        float a4[7];
        #pragma unroll
        for (int j = 0; j < 7; j++) a4[j] = 0.0f;
        #pragma unroll 4
        for (int k2 = 0; k2 < 128; k2++) {
            float2 fh = __half22float2(Ahp[k2]);
            float2 fl = __half22float2(Alp[k2]);
            float aE = fh.x + fl.x;
            float aO = fh.y + fl.y;
            const float* wE = ws + (2 * k2) * 27;
            const float* wO = wE + 27;
            #pragma unroll
            for (int j = 0; j < 7; j++) {
                int c = cj + 4 * j;
                if (c < 27) {
                    a4[j] = fmaf(aE, wE[c], a4[j]);
                    a4[j] = fmaf(aO, wO[c], a4[j]);
                }
            }
        }
        const int qg = qbase + q;
        #pragma unroll
        for (int j = 0; j < 7; j++) {
            int c = cj + 4 * j;
            if (c < 27) g_pat[qg * 27 + c] = a4[j] + __ldg(b4 + c);
        }
    }
}

// ---------------- fold3 ----------------
__global__ void fold_kernel(float* __restrict__ out) {
    int idx = blockIdx.x * blockDim.x + threadIdx.x;
    if (idx >= 2 * QN) return;
    int b = idx >> 16;
    int p = idx & (QN - 1);
    int y = p >> 8, x = p & 255;
    float s0 = 0.f, s1 = 0.f, s2 = 0.f;
    #pragma unroll
    for (int i = 0; i < 3; i++) {
        int yy = y + 1 - i;
        if (yy < 0 || yy >= HH) continue;
        #pragma unroll
        for (int j = 0; j < 3; j++) {
            int xx = x + 1 - j;
            if (xx < 0 || xx >= WWI) continue;
            const float* pp = g_pat + (b * QN + yy * WWI + xx) * 27 + i * 3 + j;
            s0 += pp[0];
            s1 += pp[9];
            s2 += pp[18];
        }
    }
    out[(b * 3 + 0) * QN + p] = s0;
    out[(b * 3 + 1) * QN + p] = s1;
    out[(b * 3 + 2) * QN + p] = s2;
}

extern "C" void kernel_launch(void* const* d_in, const int* in_sizes, int n_in,
                              void* d_out, int out_size) {
    const float* feat  = (const float*)d_in[0];
    const float* coord = (const float*)d_in[1];
    const float* w0 = (const float*)d_in[2];
    const float* b0 = (const float*)d_in[3];
    const float* w1 = (const float*)d_in[4];
    const float* b1 = (const float*)d_in[5];
    const float* w2 = (const float*)d_in[6];
    const float* b2 = (const float*)d_in[7];
    const float* w3 = (const float*)d_in[8];
    const float* b3 = (const float*)d_in[9];
    const float* w4 = (const float*)d_in[10];
    const float* b4 = (const float*)d_in[11];
    float* out = (float*)d_out;

    prep_kernel<<<(WT_ELEMS + 255) / 256, 256>>>(w0, w1, w2, w3);

    cudaFuncSetAttribute(mlp_hmma, cudaFuncAttributeMaxDynamicSharedMemorySize, SM_TOTAL);
    mlp_hmma<<<(2 * QN) / MQ, 512, SM_TOTAL>>>(feat, coord, w0, b0, b1, b2, b3, w4, b4);

    fold_kernel<<<(2 * QN + 255) / 256, 256>>>(out);
}

// round 13
// speedup vs baseline: 2.8308x; 1.2492x over previous
#include <cuda_runtime.h>
#include <cuda_fp16.h>
#include <cstdint>

// ============================================================
// LIIF_3d via HMMA 2-split (weights hi/lo, activations plain fp16):
//   z = ah*bh + ah*bl   (= ah * b exactly; error = a_lo*b ~ fp16 activation
//   rounding, empirically anchored at ~2.7e-4 final by the round-10 IMMA run)
// k32 cp.async double-buffered B staging, ONE barrier per chunk.
// MQ=128 queries/CTA, 512 threads, warp tile 32x64.
// L0 K=576 (t column = exact fp32 rank-1). L4 exact fp32 FFMA. fold3 separate.
// ============================================================

#define HH   256
#define WWI  256
#define QN   65536
#define CIN  64
#define W0F  30.0f
#define MQ   128
#define SA   264           // A row stride (halfs): 256 + 8 pad
#define SB   40            // B row stride (halfs): 32 + 8 pad (80B rows)

#define SM_COORD 0                      // qy[128] qx[128] tv[128]
#define SM_AHI   2048                   // A hi plane: 128*264*2 = 67584
#define SM_BH0   69632                  // each B plane: 256*80 = 20480
#define SM_BL0   90112
#define SM_BH1   110592
#define SM_BL1   131072
#define SM_TOTAL 151552                 // 148 KB

// transposed split weights [n][kp]: L0 256x640 (cols>=577 zero), L1-3 256x256
#define WT_ELEMS 360448
__device__ __align__(256) __half g_wt_hi[WT_ELEMS];
__device__ __align__(256) __half g_wt_lo[WT_ELEMS];
__device__ float  g_pat[2 * QN * 27];

static __device__ __forceinline__ uint32_t smem_u32(const void* p) {
    uint32_t a;
    asm("{ .reg .u64 t; cvta.to.shared.u64 t, %1; cvt.u32.u64 %0, t; }" : "=r"(a) : "l"(p));
    return a;
}

#define LDSM4(r, addr)                                                              \
    asm volatile("ldmatrix.sync.aligned.m8n8.x4.shared.b16 {%0,%1,%2,%3}, [%4];"    \
                 : "=r"((r)[0]), "=r"((r)[1]), "=r"((r)[2]), "=r"((r)[3])           \
                 : "r"(addr) : "memory")

#define CP16(dst, src) asm volatile("cp.async.cg.shared.global [%0], [%1], 16;" :: "r"(dst), "l"(src))
#define CP_COMMIT()    asm volatile("cp.async.commit_group;" ::: "memory")
#define CP_WAIT0()     asm volatile("cp.async.wait_group 0;" ::: "memory")

static __device__ __forceinline__ void mma_f32(float* c, const uint32_t* a, const uint32_t* b) {
    asm volatile(
        "mma.sync.aligned.m16n8k16.row.col.f32.f16.f16.f32 "
        "{%0,%1,%2,%3}, {%4,%5,%6,%7}, {%8,%9}, {%0,%1,%2,%3};"
        : "+f"(c[0]), "+f"(c[1]), "+f"(c[2]), "+f"(c[3])
        : "r"(a[0]), "r"(a[1]), "r"(a[2]), "r"(a[3]), "r"(b[0]), "r"(b[1]));
}

// ---------------- prep: transpose + hi/lo split ----------------
__global__ void prep_kernel(const float* __restrict__ w0, const float* __restrict__ w1,
                            const float* __restrict__ w2, const float* __restrict__ w3) {
    int i = blockIdx.x * 256 + threadIdx.x;
    if (i >= WT_ELEMS) return;
    float v;
    if (i < 163840) {                 // L0 [256][640]
        int n = i / 640, k = i - n * 640;
        v = (k < 577) ? w0[k * 256 + n] : 0.0f;
    } else if (i < 229376) {
        int j = i - 163840; int n = j >> 8, k = j & 255; v = w1[k * 256 + n];
    } else if (i < 294912) {
        int j = i - 229376; int n = j >> 8, k = j & 255; v = w2[k * 256 + n];
    } else {
        int j = i - 294912; int n = j >> 8, k = j & 255; v = w3[k * 256 + n];
    }
    __half h = __float2half_rn(v);
    g_wt_hi[i] = h;
    g_wt_lo[i] = __float2half_rn(v - __half2float(h));
}

// stage one k32 chunk of B (both planes) via cp.async; kg in halfs from layer base
static __device__ __forceinline__ void stage_b(uint32_t bh, uint32_t bl,
                                               const __half* srcH, const __half* srcL,
                                               int kp, int kg, int tid) {
    #pragma unroll
    for (int p = 0; p < 2; p++) {
        int idx = tid + p * 512;              // 0..1023 : n = idx>>2, u = idx&3
        int n = idx >> 2, u = idx & 3;
        CP16(bh + (uint32_t)(n * 80 + u * 16), srcH + n * kp + kg + u * 8);
        CP16(bl + (uint32_t)(n * 80 + u * 16), srcL + n * kp + kg + u * 8);
    }
    CP_COMMIT();
}

// ---------------- fused MLP ----------------
__global__ __launch_bounds__(512, 1)
void mlp_hmma(const float* __restrict__ feat, const float* __restrict__ coord,
              const float* __restrict__ w0_raw,
              const float* __restrict__ b0, const float* __restrict__ b1,
              const float* __restrict__ b2, const float* __restrict__ b3,
              const float* __restrict__ w4, const float* __restrict__ b4) {
    extern __shared__ char smem[];
    const uint32_t sb = smem_u32(smem);
    int*   qy = (int*)(smem + SM_COORD);
    int*   qx = qy + MQ;
    float* tv = (float*)(qx + MQ);

    const int tid  = threadIdx.x;
    const int lane = tid & 31;
    const int w    = tid >> 5;
    const int wm   = w >> 2;           // 0..3 (M groups of 32 rows)
    const int wn   = w & 3;            // 0..3 (N groups of 64 cols)
    const int qbase = blockIdx.x * MQ;
    const int bimg  = qbase >> 16;

    if (tid < MQ) {
        int qg = qbase + tid;
        int q  = qg & (QN - 1);
        const float* cp = coord + (bimg * QN + q) * 3;
        float cy = cp[0], cx = cp[1];
        const float e = 1e-6f;
        cy = fminf(fmaxf(cy, -1.0f + e), 1.0f - e);
        cx = fminf(fmaxf(cx, -1.0f + e), 1.0f - e);
        int iy = (int)rintf((cy + 1.0f) * (HH * 0.5f) - 0.5f);
        int ix = (int)rintf((cx + 1.0f) * (WWI * 0.5f) - 0.5f);
        qy[tid] = min(max(iy, 0), HH - 1);
        qx[tid] = min(max(ix, 0), WWI - 1);
        tv[tid] = cp[2];
    }
    __syncthreads();

    const float* Bias[4] = {b0, b1, b2, b3};
    const int seg[4] = {0, 163840, 229376, 294912};
    const int kps[4] = {640, 256, 256, 256};

    const int rowbase = wm * 32;
    const uint32_t a_off = (uint32_t)(((rowbase + (lane & 15)) * SA + ((lane >> 4) << 3)) * 2);
    const uint32_t aHi = sb + SM_AHI + a_off;
    const uint32_t b_off = (uint32_t)(((wn * 64 + ((lane >> 4) << 3) + (lane & 7)) * SB +
                                      ((lane >> 3) & 1) * 8) * 2);
    const uint32_t BHp[2] = {sb + SM_BH0, sb + SM_BH1};
    const uint32_t BLp[2] = {sb + SM_BL0, sb + SM_BL1};

    float acc[2][8][4];

    for (int l = 0; l < 4; l++) {
        #pragma unroll
        for (int mt = 0; mt < 2; mt++)
            #pragma unroll
            for (int nt = 0; nt < 8; nt++)
                #pragma unroll
                for (int i = 0; i < 4; i++) acc[mt][nt][i] = 0.0f;

        const int kp = kps[l];
        const __half* srcH = g_wt_hi + seg[l];
        const __half* srcL = g_wt_lo + seg[l];
        const int nstages = (l == 0) ? 3 : 1;

        for (int s = 0; s < nstages; s++) {
            const int klen = (l == 0) ? ((s < 2) ? 256 : 64) : 256;
            const int nch  = klen >> 5;            // k32 chunks
            __syncthreads();                       // A free; prev B readers done

            // prefetch chunk 0 (overlaps gather below)
            stage_b(BHp[0], BLp[0], srcH, srcL, kp, s * 256, tid);

            if (l == 0) {
                for (int idx = tid; idx < MQ * klen; idx += 512) {
                    int q = idx & (MQ - 1);
                    int j = idx >> 7;
                    int k = s * 256 + j;           // < 576
                    int ci = k / 9, r9 = k - ci * 9;
                    int di = r9 / 3, dj = r9 - di * 3;
                    int yy = qy[q] + di - 1, xx = qx[q] + dj - 1;
                    float v = (yy >= 0 && yy < HH && xx >= 0 && xx < WWI)
                        ? __ldg(feat + ((bimg * CIN + ci) * HH + yy) * WWI + xx) : 0.0f;
                    *(__half*)(smem + SM_AHI + (uint32_t)((q * SA + j) * 2)) = __float2half_rn(v);
                }
            }

            for (int c = 0; c < nch; c++) {
                CP_WAIT0();           // chunk c landed (per-thread)
                __syncthreads();      // publish chunk c; chunk c-1 readers done
                if (c + 1 < nch)      // safe now: buf[(c+1)&1] readers finished
                    stage_b(BHp[(c + 1) & 1], BLp[(c + 1) & 1], srcH, srcL,
                            kp, s * 256 + (c + 1) * 32, tid);

                const uint32_t bHi = BHp[c & 1] + b_off;
                const uint32_t bLo = BLp[c & 1] + b_off;

                #pragma unroll
                for (int ks = 0; ks < 2; ks++) {
                    const uint32_t ca2 = (uint32_t)((c * 32 + ks * 16) * 2);
                    uint32_t Ah[8];
                    LDSM4(Ah,     aHi + ca2);
                    LDSM4(Ah + 4, aHi + ca2 + 16 * SA * 2);
                    {
                        uint32_t Bh[16];
                        #pragma unroll
                        for (int p = 0; p < 4; p++)
                            LDSM4(Bh + 4 * p, bHi + (uint32_t)(p * 16 * SB * 2 + ks * 32));
                        #pragma unroll
                        for (int mt = 0; mt < 2; mt++)
                            #pragma unroll
                            for (int nt = 0; nt < 8; nt++)
                                mma_f32(acc[mt][nt], Ah + 4 * mt, Bh + 2 * nt);
                    }
                    {
                        uint32_t Bl[16];
                        #pragma unroll
                        for (int p = 0; p < 4; p++)
                            LDSM4(Bl + 4 * p, bLo + (uint32_t)(p * 16 * SB * 2 + ks * 32));
                        #pragma unroll
                        for (int mt = 0; mt < 2; mt++)
                            #pragma unroll
                            for (int nt = 0; nt < 8; nt++)
                                mma_f32(acc[mt][nt], Ah + 4 * mt, Bl + 2 * nt);
                    }
                }
            }
        }

        __syncthreads();   // all warps done reading A before epilogue overwrites it
        {
            const float* bp = Bias[l];
            const int trow  = rowbase + (lane >> 2);
            const int tcol0 = wn * 64 + 2 * (lane & 3);
            #pragma unroll
            for (int mt = 0; mt < 2; mt++) {
                const int r0 = trow + mt * 16;
                const int r1 = r0 + 8;
                const float tv0 = tv[r0], tv1 = tv[r1];
                #pragma unroll
                for (int nt = 0; nt < 8; nt++) {
                    int col = tcol0 + nt * 8;
                    float2 bb = *(const float2*)(bp + col);
                    float a0 = acc[mt][nt][0], a1 = acc[mt][nt][1];
                    float a2 = acc[mt][nt][2], a3 = acc[mt][nt][3];
                    if (l == 0) {   // exact rank-1 t-term: tv * w0[576,:]
                        float wa = __ldg(w0_raw + 576 * 256 + col);
                        float wb = __ldg(w0_raw + 576 * 256 + col + 1);
                        a0 = fmaf(tv0, wa, a0); a1 = fmaf(tv0, wb, a1);
                        a2 = fmaf(tv1, wa, a2); a3 = fmaf(tv1, wb, a3);
                    }
                    float v00 = __sinf(W0F * (a0 + bb.x));
                    float v01 = __sinf(W0F * (a1 + bb.y));
                    float v10 = __sinf(W0F * (a2 + bb.x));
                    float v11 = __sinf(W0F * (a3 + bb.y));
                    uint32_t o0 = (uint32_t)((r0 * SA + col) * 2);
                    uint32_t o1 = (uint32_t)((r1 * SA + col) * 2);
                    *(__half2*)(smem + SM_AHI + o0) =
                        __halves2half2(__float2half_rn(v00), __float2half_rn(v01));
                    *(__half2*)(smem + SM_AHI + o1) =
                        __halves2half2(__float2half_rn(v10), __float2half_rn(v11));
                }
            }
        }
    }

    // ---------------- L4: 256 -> 27 in fp32 FFMA (half2 A reads) ----------------
    {
        __syncthreads();                          // L3 epilogues visible; B area free
        float* ws = (float*)(smem + SM_BH0);      // 256*27 floats = 27648B
        for (int i = tid; i < 256 * 27; i += 512) ws[i] = __ldg(w4 + i);
        __syncthreads();

        const int q  = tid >> 2;                  // 0..127
        const int cj = tid & 3;
        const __half2* Ahp = (const __half2*)((const __half*)(smem + SM_AHI) + q * SA);
        float a4[7];
        #pragma unroll
        for (int j = 0; j < 7; j++) a4[j] = 0.0f;
        #pragma unroll 4
        for (int k2 = 0; k2 < 128; k2++) {
            float2 fh = __half22float2(Ahp[k2]);
            const float* wE = ws + (2 * k2) * 27;
            const float* wO = wE + 27;
            #pragma unroll
            for (int j = 0; j < 7; j++) {
                int c = cj + 4 * j;
                if (c < 27) {
                    a4[j] = fmaf(fh.x, wE[c], a4[j]);
                    a4[j] = fmaf(fh.y, wO[c], a4[j]);
                }
            }
        }
        const int qg = qbase + q;
        #pragma unroll
        for (int j = 0; j < 7; j++) {
            int c = cj + 4 * j;
            if (c < 27) g_pat[qg * 27 + c] = a4[j] + __ldg(b4 + c);
        }
    }
}

// ---------------- fold3 ----------------
__global__ void fold_kernel(float* __restrict__ out) {
    int idx = blockIdx.x * blockDim.x + threadIdx.x;
    if (idx >= 2 * QN) return;
    int b = idx >> 16;
    int p = idx & (QN - 1);
    int y = p >> 8, x = p & 255;
    float s0 = 0.f, s1 = 0.f, s2 = 0.f;
    #pragma unroll
    for (int i = 0; i < 3; i++) {
        int yy = y + 1 - i;
        if (yy < 0 || yy >= HH) continue;
        #pragma unroll
        for (int j = 0; j < 3; j++) {
            int xx = x + 1 - j;
            if (xx < 0 || xx >= WWI) continue;
            const float* pp = g_pat + (b * QN + yy * WWI + xx) * 27 + i * 3 + j;
            s0 += pp[0];
            s1 += pp[9];
            s2 += pp[18];
        }
    }
    out[(b * 3 + 0) * QN + p] = s0;
    out[(b * 3 + 1) * QN + p] = s1;
    out[(b * 3 + 2) * QN + p] = s2;
}

extern "C" void kernel_launch(void* const* d_in, const int* in_sizes, int n_in,
                              void* d_out, int out_size) {
    const float* feat  = (const float*)d_in[0];
    const float* coord = (const float*)d_in[1];
    const float* w0 = (const float*)d_in[2];
    const float* b0 = (const float*)d_in[3];
    const float* w1 = (const float*)d_in[4];
    const float* b1 = (const float*)d_in[5];
    const float* w2 = (const float*)d_in[6];
    const float* b2 = (const float*)d_in[7];
    const float* w3 = (const float*)d_in[8];
    const float* b3 = (const float*)d_in[9];
    const float* w4 = (const float*)d_in[10];
    const float* b4 = (const float*)d_in[11];
    float* out = (float*)d_out;

    prep_kernel<<<(WT_ELEMS + 255) / 256, 256>>>(w0, w1, w2, w3);

    cudaFuncSetAttribute(mlp_hmma, cudaFuncAttributeMaxDynamicSharedMemorySize, SM_TOTAL);
    mlp_hmma<<<(2 * QN) / MQ, 512, SM_TOTAL>>>(feat, coord, w0, b0, b1, b2, b3, w4, b4);

    fold_kernel<<<(2 * QN + 255) / 256, 256>>>(out);
}

// round 14
// speedup vs baseline: 2.9344x; 1.0366x over previous
#include <cuda_runtime.h>
#include <cuda_fp16.h>
#include <cstdint>

// ============================================================
// LIIF_3d via HMMA 2-split (weights hi/lo, activations fp16).
// Round 14: overhead-overlap restructure (numerics identical to round 13):
//  - A double-buffer (A0/A1); L0 gather sliced INTO the chunk MMA stream
//  - one global chunk pipeline across stages/layers (prefetch next chunk
//    inside current body, incl. across layer boundaries)
//  - epilogue ping-pongs activation buffer -> pre-epilogue barriers deleted
//  - L4 weights staged via cp.async during the last L3 chunk
// MQ=128 queries/CTA, 512 threads, warp tile 32x64, k32 chunks.
// L0 K=576 (t = exact fp32 rank-1). L4 exact fp32 FFMA. fold3 separate.
// ============================================================

#define HH   256
#define WWI  256
#define QN   65536
#define CIN  64
#define W0F  30.0f
#define MQ   128
#define SA   264           // A row stride (halfs): 256 + 8 pad
#define SB   40            // B row stride (halfs): 32 + 8 pad (80B rows)

#define SM_COORD 0                      // qy[128] qx[128] tv[128]
#define SM_A0    2048                   // A plane 0: 128*264*2 = 67584
#define SM_A1    69632                  // A plane 1
#define SM_BH0   137216                 // each B plane: 256*80 = 20480
#define SM_BL0   157696                 // (BH0+BL0 contiguous 40960B -> L4 ws)
#define SM_BH1   178176
#define SM_BL1   198656
#define SM_TOTAL 219136                 // 214 KB (round-9-proven)

// transposed split weights [n][kp]: L0 256x640 (cols>=577 zero), L1-3 256x256
#define WT_ELEMS 360448
__device__ __align__(256) __half g_wt_hi[WT_ELEMS];
__device__ __align__(256) __half g_wt_lo[WT_ELEMS];
__device__ float  g_pat[2 * QN * 27];

static __device__ __forceinline__ uint32_t smem_u32(const void* p) {
    uint32_t a;
    asm("{ .reg .u64 t; cvta.to.shared.u64 t, %1; cvt.u32.u64 %0, t; }" : "=r"(a) : "l"(p));
    return a;
}

#define LDSM4(r, addr)                                                              \
    asm volatile("ldmatrix.sync.aligned.m8n8.x4.shared.b16 {%0,%1,%2,%3}, [%4];"    \
                 : "=r"((r)[0]), "=r"((r)[1]), "=r"((r)[2]), "=r"((r)[3])           \
                 : "r"(addr) : "memory")

#define CP16(dst, src) asm volatile("cp.async.cg.shared.global [%0], [%1], 16;" :: "r"(dst), "l"(src))
#define CP_COMMIT()    asm volatile("cp.async.commit_group;" ::: "memory")
#define CP_WAIT0()     asm volatile("cp.async.wait_group 0;" ::: "memory")

static __device__ __forceinline__ void mma_f32(float* c, const uint32_t* a, const uint32_t* b) {
    asm volatile(
        "mma.sync.aligned.m16n8k16.row.col.f32.f16.f16.f32 "
        "{%0,%1,%2,%3}, {%4,%5,%6,%7}, {%8,%9}, {%0,%1,%2,%3};"
        : "+f"(c[0]), "+f"(c[1]), "+f"(c[2]), "+f"(c[3])
        : "r"(a[0]), "r"(a[1]), "r"(a[2]), "r"(a[3]), "r"(b[0]), "r"(b[1]));
}

// ---------------- prep: transpose + hi/lo split ----------------
__global__ void prep_kernel(const float* __restrict__ w0, const float* __restrict__ w1,
                            const float* __restrict__ w2, const float* __restrict__ w3) {
    int i = blockIdx.x * 256 + threadIdx.x;
    if (i >= WT_ELEMS) return;
    float v;
    if (i < 163840) {                 // L0 [256][640]
        int n = i / 640, k = i - n * 640;
        v = (k < 577) ? w0[k * 256 + n] : 0.0f;
    } else if (i < 229376) {
        int j = i - 163840; int n = j >> 8, k = j & 255; v = w1[k * 256 + n];
    } else if (i < 294912) {
        int j = i - 229376; int n = j >> 8, k = j & 255; v = w2[k * 256 + n];
    } else {
        int j = i - 294912; int n = j >> 8, k = j & 255; v = w3[k * 256 + n];
    }
    __half h = __float2half_rn(v);
    g_wt_hi[i] = h;
    g_wt_lo[i] = __float2half_rn(v - __half2float(h));
}

// stage one k32 chunk of B (both planes) via cp.async; kg in halfs
static __device__ __forceinline__ void stage_b(uint32_t bh, uint32_t bl,
                                               const __half* srcH, const __half* srcL,
                                               int kp, int kg, int tid) {
    #pragma unroll
    for (int p = 0; p < 2; p++) {
        int idx = tid + p * 512;              // 0..1023 : n = idx>>2, u = idx&3
        int n = idx >> 2, u = idx & 3;
        CP16(bh + (uint32_t)(n * 80 + u * 16), srcH + n * kp + kg + u * 8);
        CP16(bl + (uint32_t)(n * 80 + u * 16), srcL + n * kp + kg + u * 8);
    }
    CP_COMMIT();
}

// ---------------- fused MLP ----------------
__global__ __launch_bounds__(512, 1)
void mlp_hmma(const float* __restrict__ feat, const float* __restrict__ coord,
              const float* __restrict__ w0_raw,
              const float* __restrict__ b0, const float* __restrict__ b1,
              const float* __restrict__ b2, const float* __restrict__ b3,
              const float* __restrict__ w4, const float* __restrict__ b4) {
    extern __shared__ char smem[];
    const uint32_t sb = smem_u32(smem);
    int*   qy = (int*)(smem + SM_COORD);
    int*   qx = qy + MQ;
    float* tv = (float*)(qx + MQ);

    const int tid  = threadIdx.x;
    const int lane = tid & 31;
    const int w    = tid >> 5;
    const int wm   = w >> 2;           // 0..3 (M groups of 32 rows)
    const int wn   = w & 3;            // 0..3 (N groups of 64 cols)
    const int qbase = blockIdx.x * MQ;
    const int bimg  = qbase >> 16;

    if (tid < MQ) {
        int qg = qbase + tid;
        int q  = qg & (QN - 1);
        const float* cp = coord + (bimg * QN + q) * 3;
        float cy = cp[0], cx = cp[1];
        const float e = 1e-6f;
        cy = fminf(fmaxf(cy, -1.0f + e), 1.0f - e);
        cx = fminf(fmaxf(cx, -1.0f + e), 1.0f - e);
        int iy = (int)rintf((cy + 1.0f) * (HH * 0.5f) - 0.5f);
        int ix = (int)rintf((cx + 1.0f) * (WWI * 0.5f) - 0.5f);
        qy[tid] = min(max(iy, 0), HH - 1);
        qx[tid] = min(max(ix, 0), WWI - 1);
        tv[tid] = cp[2];
    }
    __syncthreads();

    // gather ncols L0 columns starting at global k0 into buffer at byte base ab
    auto gather_range = [&](int k0, int ncols, uint32_t ab) {
        for (int idx = tid; idx < MQ * ncols; idx += 512) {
            int q = idx & (MQ - 1);
            int k = k0 + (idx >> 7);           // < 576
            int ci = k / 9, r9 = k - ci * 9;
            int di = r9 / 3, dj = r9 - di * 3;
            int yy = qy[q] + di - 1, xx = qx[q] + dj - 1;
            float v = (yy >= 0 && yy < HH && xx >= 0 && xx < WWI)
                ? __ldg(feat + ((bimg * CIN + ci) * HH + yy) * WWI + xx) : 0.0f;
            *(__half*)(smem + ab + (uint32_t)((q * SA + (k & 255)) * 2)) = __float2half_rn(v);
        }
    };

    const float* Bias[4] = {b0, b1, b2, b3};
    const int seg[4] = {0, 163840, 229376, 294912};
    const int kps[4] = {640, 256, 256, 256};
    const int KL[4]  = {576, 256, 256, 256};

    const int rowbase = wm * 32;
    const uint32_t a_off = (uint32_t)(((rowbase + (lane & 15)) * SA + ((lane >> 4) << 3)) * 2);
    const uint32_t b_off = (uint32_t)(((wn * 64 + ((lane >> 4) << 3) + (lane & 7)) * SB +
                                      ((lane >> 3) & 1) * 8) * 2);
    const uint32_t BHp[2] = {sb + SM_BH0, sb + SM_BH1};
    const uint32_t BLp[2] = {sb + SM_BL0, sb + SM_BL1};

    // prefetch very first chunk (L0, kg=0) into buffer 0
    stage_b(BHp[0], BLp[0], g_wt_hi, g_wt_lo, 640, 0, tid);
    // exposed initial gather: L0 stage 0 (cols 0..255) -> A0
    gather_range(0, 256, SM_A0);

    float acc[2][8][4];
    int pb = 0;

    for (int l = 0; l < 4; l++) {
        #pragma unroll
        for (int mt = 0; mt < 2; mt++)
            #pragma unroll
            for (int nt = 0; nt < 8; nt++)
                #pragma unroll
                for (int i = 0; i < 4; i++) acc[mt][nt][i] = 0.0f;

        for (int kg = 0; kg < KL[l]; kg += 32) {
            CP_WAIT0();           // current chunk landed (per-thread)
            __syncthreads();      // publish chunk; prev-chunk readers + epilogue/gather visible

            // prefetch next chunk in the GLOBAL sequence (crosses stage/layer)
            {
                int nl = l, nkg = kg + 32;
                if (nkg >= KL[l]) { nl = l + 1; nkg = 0; }
                if (nl < 4) {
                    stage_b(BHp[pb ^ 1], BLp[pb ^ 1],
                            g_wt_hi + seg[nl], g_wt_lo + seg[nl], kps[nl], nkg, tid);
                } else {
                    // last chunk (l=3,kg=224): pb==1 -> buffer 0 free; stage L4 ws there
                    for (int i = tid; i < 1728; i += 512)          // 27648B of w4
                        CP16(sb + SM_BH0 + (uint32_t)(i * 16), (const char*)w4 + i * 16);
                    CP_COMMIT();
                }
            }

            // A buffer for this chunk: L0 stages ping-pong A0/A1; layers 1-3 ping-pong
            const uint32_t Ab = (l == 0) ? (((kg >> 8) & 1) ? (uint32_t)SM_A1 : (uint32_t)SM_A0)
                                         : ((l & 1) ? (uint32_t)SM_A1 : (uint32_t)SM_A0);
            const uint32_t aHi = sb + Ab + a_off;
            const uint32_t bHi = BHp[pb] + b_off;
            const uint32_t bLo = BLp[pb] + b_off;

            #pragma unroll
            for (int ks = 0; ks < 2; ks++) {
                const uint32_t ca2 = (uint32_t)(((kg & 255) + ks * 16) * 2);
                uint32_t Ah[8];
                LDSM4(Ah,     aHi + ca2);
                LDSM4(Ah + 4, aHi + ca2 + 16 * SA * 2);
                {
                    uint32_t Bh[16];
                    #pragma unroll
                    for (int p = 0; p < 4; p++)
                        LDSM4(Bh + 4 * p, bHi + (uint32_t)(p * 16 * SB * 2 + ks * 32));
                    #pragma unroll
                    for (int mt = 0; mt < 2; mt++)
                        #pragma unroll
                        for (int nt = 0; nt < 8; nt++)
                            mma_f32(acc[mt][nt], Ah + 4 * mt, Bh + 2 * nt);
                }
                {
                    uint32_t Bl[16];
                    #pragma unroll
                    for (int p = 0; p < 4; p++)
                        LDSM4(Bl + 4 * p, bLo + (uint32_t)(p * 16 * SB * 2 + ks * 32));
                    #pragma unroll
                    for (int mt = 0; mt < 2; mt++)
                        #pragma unroll
                        for (int nt = 0; nt < 8; nt++)
                            mma_f32(acc[mt][nt], Ah + 4 * mt, Bl + 2 * nt);
                }
            }

            // interleave next-stage gather slices into the MMA stream (L0 only)
            if (l == 0) {
                int s = kg >> 8, c = (kg >> 5) & 7;
                if (s == 0)      gather_range(256 + c * 32, 32, SM_A1);
                else if (s == 1) gather_range(512 + c * 8,   8, SM_A0);
            }

            pb ^= 1;
        }

        // ---- epilogue: NO barrier (acc is warp-local; writes go to the
        //      OPPOSITE A buffer, which has no outstanding readers) ----
        {
            const uint32_t Wb = (l & 1) ? (uint32_t)SM_A0 : (uint32_t)SM_A1;  // l0->A1,l1->A0,l2->A1,l3->A0
            const float* bp = Bias[l];
            const int trow  = rowbase + (lane >> 2);
            const int tcol0 = wn * 64 + 2 * (lane & 3);
            #pragma unroll
            for (int mt = 0; mt < 2; mt++) {
                const int r0 = trow + mt * 16;
                const int r1 = r0 + 8;
                const float tv0 = tv[r0], tv1 = tv[r1];
                #pragma unroll
                for (int nt = 0; nt < 8; nt++) {
                    int col = tcol0 + nt * 8;
                    float2 bb = *(const float2*)(bp + col);
                    float a0 = acc[mt][nt][0], a1 = acc[mt][nt][1];
                    float a2 = acc[mt][nt][2], a3 = acc[mt][nt][3];
                    if (l == 0) {   // exact rank-1 t-term: tv * w0[576,:]
                        float wa = __ldg(w0_raw + 576 * 256 + col);
                        float wb = __ldg(w0_raw + 576 * 256 + col + 1);
                        a0 = fmaf(tv0, wa, a0); a1 = fmaf(tv0, wb, a1);
                        a2 = fmaf(tv1, wa, a2); a3 = fmaf(tv1, wb, a3);
                    }
                    float v00 = __sinf(W0F * (a0 + bb.x));
                    float v01 = __sinf(W0F * (a1 + bb.y));
                    float v10 = __sinf(W0F * (a2 + bb.x));
                    float v11 = __sinf(W0F * (a3 + bb.y));
                    uint32_t o0 = (uint32_t)((r0 * SA + col) * 2);
                    uint32_t o1 = (uint32_t)((r1 * SA + col) * 2);
                    *(__half2*)(smem + Wb + o0) =
                        __halves2half2(__float2half_rn(v00), __float2half_rn(v01));
                    *(__half2*)(smem + Wb + o1) =
                        __halves2half2(__float2half_rn(v10), __float2half_rn(v11));
                }
            }
        }
    }

    // ---------------- L4: 256 -> 27 in fp32 FFMA ----------------
    {
        CP_WAIT0();                               // ws landed
        __syncthreads();                          // L3 epilogue (A0) + ws visible
        const float* ws = (const float*)(smem + SM_BH0);   // 256*27 floats

        const int q  = tid >> 2;                  // 0..127
        const int cj = tid & 3;
        const __half2* Ahp = (const __half2*)((const __half*)(smem + SM_A0) + q * SA);
        float a4[7];
        #pragma unroll
        for (int j = 0; j < 7; j++) a4[j] = 0.0f;
        #pragma unroll 4
        for (int k2 = 0; k2 < 128; k2++) {
            float2 fh = __half22float2(Ahp[k2]);
            const float* wE = ws + (2 * k2) * 27;
            const float* wO = wE + 27;
            #pragma unroll
            for (int j = 0; j < 7; j++) {
                int c = cj + 4 * j;
                if (c < 27) {
                    a4[j] = fmaf(fh.x, wE[c], a4[j]);
                    a4[j] = fmaf(fh.y, wO[c], a4[j]);
                }
            }
        }
        const int qg = qbase + q;
        #pragma unroll
        for (int j = 0; j < 7; j++) {
            int c = cj + 4 * j;
            if (c < 27) g_pat[qg * 27 + c] = a4[j] + __ldg(b4 + c);
        }
    }
}

// ---------------- fold3 ----------------
__global__ void fold_kernel(float* __restrict__ out) {
    int idx = blockIdx.x * blockDim.x + threadIdx.x;
    if (idx >= 2 * QN) return;
    int b = idx >> 16;
    int p = idx & (QN - 1);
    int y = p >> 8, x = p & 255;
    float s0 = 0.f, s1 = 0.f, s2 = 0.f;
    #pragma unroll
    for (int i = 0; i < 3; i++) {
        int yy = y + 1 - i;
        if (yy < 0 || yy >= HH) continue;
        #pragma unroll
        for (int j = 0; j < 3; j++) {
            int xx = x + 1 - j;
            if (xx < 0 || xx >= WWI) continue;
            const float* pp = g_pat + (b * QN + yy * WWI + xx) * 27 + i * 3 + j;
            s0 += pp[0];
            s1 += pp[9];
            s2 += pp[18];
        }
    }
    out[(b * 3 + 0) * QN + p] = s0;
    out[(b * 3 + 1) * QN + p] = s1;
    out[(b * 3 + 2) * QN + p] = s2;
}

extern "C" void kernel_launch(void* const* d_in, const int* in_sizes, int n_in,
                              void* d_out, int out_size) {
    const float* feat  = (const float*)d_in[0];
    const float* coord = (const float*)d_in[1];
    const float* w0 = (const float*)d_in[2];
    const float* b0 = (const float*)d_in[3];
    const float* w1 = (const float*)d_in[4];
    const float* b1 = (const float*)d_in[5];
    const float* w2 = (const float*)d_in[6];
    const float* b2 = (const float*)d_in[7];
    const float* w3 = (const float*)d_in[8];
    const float* b3 = (const float*)d_in[9];
    const float* w4 = (const float*)d_in[10];
    const float* b4 = (const float*)d_in[11];
    float* out = (float*)d_out;

    prep_kernel<<<(WT_ELEMS + 255) / 256, 256>>>(w0, w1, w2, w3);

    cudaFuncSetAttribute(mlp_hmma, cudaFuncAttributeMaxDynamicSharedMemorySize, SM_TOTAL);
    mlp_hmma<<<(2 * QN) / MQ, 512, SM_TOTAL>>>(feat, coord, w0, b0, b1, b2, b3, w4, b4);

    fold_kernel<<<(2 * QN + 255) / 256, 256>>>(out);
}

// round 15
// speedup vs baseline: 3.3149x; 1.1297x over previous
#include <cuda_runtime.h>
#include <cuda_fp16.h>
#include <cstdint>

// ============================================================
// LIIF_3d via HMMA 2-split (weights hi/lo, activations fp16).
// Round 15 vs round 14:
//  - L4 (256->27) moved to HMMA (16 warps x 16x16 tiles; B staged via the
//    existing chunk-pipeline slot during the last L3 chunk) — was 14K cyc
//    of serial fp32 FFMA, now ~4K cyc of tensor work.
//  - stage-0 gather fully in-stream (exposed prologue = 32 cols only).
// MQ=128 queries/CTA, 512 threads, warp tile 32x64, k32 chunks,
// one barrier per chunk. L0 K=576 (t = exact fp32 rank-1). fold3 separate.
// ============================================================

#define HH   256
#define WWI  256
#define QN   65536
#define CIN  64
#define W0F  30.0f
#define MQ   128
#define SA   264           // A row stride (halfs): 256 + 8 pad
#define SB   40            // B row stride (halfs): 32 + 8 pad (80B rows)
#define SB4  264           // L4 B row stride (halfs): 256 + 8 pad

#define SM_COORD 0                      // qy[128] qx[128] tv[128]
#define SM_A0    2048                   // A plane 0: 128*264*2 = 67584
#define SM_A1    69632                  // A plane 1
#define SM_BH0   137216                 // each B plane: 256*80 = 20480
#define SM_BL0   157696                 // (L4 B hi/lo reuse BH0/BL0: 32*528=16896 each)
#define SM_BH1   178176
#define SM_BL1   198656
#define SM_TOTAL 219136                 // 214 KB

// transposed split weights [n][kp]: L0 256x640 (cols>=577 zero), L1-3 256x256,
// L4 32x256 (rows>=27 zero)
#define WT_ELEMS 368640
__device__ __align__(256) __half g_wt_hi[WT_ELEMS];
__device__ __align__(256) __half g_wt_lo[WT_ELEMS];
__device__ float  g_pat[2 * QN * 27];

static __device__ __forceinline__ uint32_t smem_u32(const void* p) {
    uint32_t a;
    asm("{ .reg .u64 t; cvta.to.shared.u64 t, %1; cvt.u32.u64 %0, t; }" : "=r"(a) : "l"(p));
    return a;
}

#define LDSM4(r, addr)                                                              \
    asm volatile("ldmatrix.sync.aligned.m8n8.x4.shared.b16 {%0,%1,%2,%3}, [%4];"    \
                 : "=r"((r)[0]), "=r"((r)[1]), "=r"((r)[2]), "=r"((r)[3])           \
                 : "r"(addr) : "memory")

#define CP16(dst, src) asm volatile("cp.async.cg.shared.global [%0], [%1], 16;" :: "r"(dst), "l"(src))
#define CP_COMMIT()    asm volatile("cp.async.commit_group;" ::: "memory")
#define CP_WAIT0()     asm volatile("cp.async.wait_group 0;" ::: "memory")

static __device__ __forceinline__ void mma_f32(float* c, const uint32_t* a, const uint32_t* b) {
    asm volatile(
        "mma.sync.aligned.m16n8k16.row.col.f32.f16.f16.f32 "
        "{%0,%1,%2,%3}, {%4,%5,%6,%7}, {%8,%9}, {%0,%1,%2,%3};"
        : "+f"(c[0]), "+f"(c[1]), "+f"(c[2]), "+f"(c[3])
        : "r"(a[0]), "r"(a[1]), "r"(a[2]), "r"(a[3]), "r"(b[0]), "r"(b[1]));
}

// ---------------- prep: transpose + hi/lo split ----------------
__global__ void prep_kernel(const float* __restrict__ w0, const float* __restrict__ w1,
                            const float* __restrict__ w2, const float* __restrict__ w3,
                            const float* __restrict__ w4) {
    int i = blockIdx.x * 256 + threadIdx.x;
    if (i >= WT_ELEMS) return;
    float v;
    if (i < 163840) {                 // L0 [256][640]
        int n = i / 640, k = i - n * 640;
        v = (k < 577) ? w0[k * 256 + n] : 0.0f;
    } else if (i < 229376) {
        int j = i - 163840; int n = j >> 8, k = j & 255; v = w1[k * 256 + n];
    } else if (i < 294912) {
        int j = i - 229376; int n = j >> 8, k = j & 255; v = w2[k * 256 + n];
    } else if (i < 360448) {
        int j = i - 294912; int n = j >> 8, k = j & 255; v = w3[k * 256 + n];
    } else {                          // L4 [32][256], rows >= 27 zero
        int j = i - 360448; int n = j >> 8, k = j & 255;
        v = (n < 27) ? w4[k * 27 + n] : 0.0f;
    }
    __half h = __float2half_rn(v);
    g_wt_hi[i] = h;
    g_wt_lo[i] = __float2half_rn(v - __half2float(h));
}

// stage one k32 chunk of B (both planes) via cp.async; kg in halfs
static __device__ __forceinline__ void stage_b(uint32_t bh, uint32_t bl,
                                               const __half* srcH, const __half* srcL,
                                               int kp, int kg, int tid) {
    #pragma unroll
    for (int p = 0; p < 2; p++) {
        int idx = tid + p * 512;              // 0..1023 : n = idx>>2, u = idx&3
        int n = idx >> 2, u = idx & 3;
        CP16(bh + (uint32_t)(n * 80 + u * 16), srcH + n * kp + kg + u * 8);
        CP16(bl + (uint32_t)(n * 80 + u * 16), srcL + n * kp + kg + u * 8);
    }
    CP_COMMIT();
}

// ---------------- fused MLP ----------------
__global__ __launch_bounds__(512, 1)
void mlp_hmma(const float* __restrict__ feat, const float* __restrict__ coord,
              const float* __restrict__ w0_raw,
              const float* __restrict__ b0, const float* __restrict__ b1,
              const float* __restrict__ b2, const float* __restrict__ b3,
              const float* __restrict__ b4) {
    extern __shared__ char smem[];
    const uint32_t sb = smem_u32(smem);
    int*   qy = (int*)(smem + SM_COORD);
    int*   qx = qy + MQ;
    float* tv = (float*)(qx + MQ);

    const int tid  = threadIdx.x;
    const int lane = tid & 31;
    const int w    = tid >> 5;
    const int wm   = w >> 2;           // 0..3 (M groups of 32 rows)
    const int wn   = w & 3;            // 0..3 (N groups of 64 cols)
    const int qbase = blockIdx.x * MQ;
    const int bimg  = qbase >> 16;

    if (tid < MQ) {
        int qg = qbase + tid;
        int q  = qg & (QN - 1);
        const float* cp = coord + (bimg * QN + q) * 3;
        float cy = cp[0], cx = cp[1];
        const float e = 1e-6f;
        cy = fminf(fmaxf(cy, -1.0f + e), 1.0f - e);
        cx = fminf(fmaxf(cx, -1.0f + e), 1.0f - e);
        int iy = (int)rintf((cy + 1.0f) * (HH * 0.5f) - 0.5f);
        int ix = (int)rintf((cx + 1.0f) * (WWI * 0.5f) - 0.5f);
        qy[tid] = min(max(iy, 0), HH - 1);
        qx[tid] = min(max(ix, 0), WWI - 1);
        tv[tid] = cp[2];
    }
    __syncthreads();

    // gather ncols L0 columns starting at global k0 into buffer at byte base ab
    auto gather_range = [&](int k0, int ncols, uint32_t ab) {
        for (int idx = tid; idx < MQ * ncols; idx += 512) {
            int q = idx & (MQ - 1);
            int k = k0 + (idx >> 7);           // < 576
            int ci = k / 9, r9 = k - ci * 9;
            int di = r9 / 3, dj = r9 - di * 3;
            int yy = qy[q] + di - 1, xx = qx[q] + dj - 1;
            float v = (yy >= 0 && yy < HH && xx >= 0 && xx < WWI)
                ? __ldg(feat + ((bimg * CIN + ci) * HH + yy) * WWI + xx) : 0.0f;
            *(__half*)(smem + ab + (uint32_t)((q * SA + (k & 255)) * 2)) = __float2half_rn(v);
        }
    };

    const float* Bias[4] = {b0, b1, b2, b3};
    const int seg[4] = {0, 163840, 229376, 294912};
    const int kps[4] = {640, 256, 256, 256};
    const int KL[4]  = {576, 256, 256, 256};

    const int rowbase = wm * 32;
    const uint32_t a_off = (uint32_t)(((rowbase + (lane & 15)) * SA + ((lane >> 4) << 3)) * 2);
    const uint32_t b_off = (uint32_t)(((wn * 64 + ((lane >> 4) << 3) + (lane & 7)) * SB +
                                      ((lane >> 3) & 1) * 8) * 2);
    const uint32_t BHp[2] = {sb + SM_BH0, sb + SM_BH1};
    const uint32_t BLp[2] = {sb + SM_BL0, sb + SM_BL1};

    // prefetch very first chunk (L0, kg=0) into buffer 0
    stage_b(BHp[0], BLp[0], g_wt_hi, g_wt_lo, 640, 0, tid);
    // exposed initial gather: ONLY cols 0..31 (rest is pipelined in-stream)
    gather_range(0, 32, SM_A0);

    float acc[2][8][4];
    int pb = 0;

    for (int l = 0; l < 4; l++) {
        #pragma unroll
        for (int mt = 0; mt < 2; mt++)
            #pragma unroll
            for (int nt = 0; nt < 8; nt++)
                #pragma unroll
                for (int i = 0; i < 4; i++) acc[mt][nt][i] = 0.0f;

        for (int kg = 0; kg < KL[l]; kg += 32) {
            CP_WAIT0();           // current chunk landed (per-thread)
            __syncthreads();      // publish chunk + gathered cols; prev readers done

            // prefetch next chunk in the GLOBAL sequence (crosses stage/layer)
            {
                int nl = l, nkg = kg + 32;
                if (nkg >= KL[l]) { nl = l + 1; nkg = 0; }
                if (nl < 4) {
                    stage_b(BHp[pb ^ 1], BLp[pb ^ 1],
                            g_wt_hi + seg[nl], g_wt_lo + seg[nl], kps[nl], nkg, tid);
                } else {
                    // last chunk (l=3,kg=224): pb==1 -> buffer 0 free; stage L4 B
                    // [32 n][256 k] hi/lo with row stride SB4=264 halfs (528B)
                    #pragma unroll
                    for (int p = 0; p < 4; p++) {
                        int idx = tid + p * 512;          // 0..2047
                        int pl = idx >> 10;               // 0: hi, 1: lo
                        int r  = idx & 1023;              // n = r>>5, u = r&31
                        int n = r >> 5, u = r & 31;
                        const __half* src = (pl ? g_wt_lo : g_wt_hi) + 360448 + n * 256 + u * 8;
                        uint32_t dst = (pl ? (sb + SM_BL0) : (sb + SM_BH0))
                                       + (uint32_t)(n * 528 + u * 16);
                        CP16(dst, src);
                    }
                    CP_COMMIT();
                }
            }

            // A buffer for this chunk
            const uint32_t Ab = (l == 0) ? (((kg >> 8) & 1) ? (uint32_t)SM_A1 : (uint32_t)SM_A0)
                                         : ((l & 1) ? (uint32_t)SM_A1 : (uint32_t)SM_A0);
            const uint32_t aHi = sb + Ab + a_off;
            const uint32_t bHi = BHp[pb] + b_off;
            const uint32_t bLo = BLp[pb] + b_off;

            #pragma unroll
            for (int ks = 0; ks < 2; ks++) {
                const uint32_t ca2 = (uint32_t)(((kg & 255) + ks * 16) * 2);
                uint32_t Ah[8];
                LDSM4(Ah,     aHi + ca2);
                LDSM4(Ah + 4, aHi + ca2 + 16 * SA * 2);
                {
                    uint32_t Bh[16];
                    #pragma unroll
                    for (int p = 0; p < 4; p++)
                        LDSM4(Bh + 4 * p, bHi + (uint32_t)(p * 16 * SB * 2 + ks * 32));
                    #pragma unroll
                    for (int mt = 0; mt < 2; mt++)
                        #pragma unroll
                        for (int nt = 0; nt < 8; nt++)
                            mma_f32(acc[mt][nt], Ah + 4 * mt, Bh + 2 * nt);
                }
                {
                    uint32_t Bl[16];
                    #pragma unroll
                    for (int p = 0; p < 4; p++)
                        LDSM4(Bl + 4 * p, bLo + (uint32_t)(p * 16 * SB * 2 + ks * 32));
                    #pragma unroll
                    for (int mt = 0; mt < 2; mt++)
                        #pragma unroll
                        for (int nt = 0; nt < 8; nt++)
                            mma_f32(acc[mt][nt], Ah + 4 * mt, Bl + 2 * nt);
                }
            }

            // interleaved gathers (L0 only), published by the NEXT chunk's barrier
            if (l == 0) {
                int c = kg >> 5;                    // 0..17
                if (kg < 256) {                     // stage-0 bodies
                    if (c < 7) gather_range(32 * (c + 1), 32, SM_A0);
                    gather_range(256 + c * 32, 32, SM_A1);
                } else if (kg < 512) {              // stage-1 bodies
                    gather_range(512 + (c - 8) * 8, 8, SM_A0);
                }
            }

            pb ^= 1;
        }

        // ---- epilogue: no barrier; writes go to the OPPOSITE A buffer ----
        {
            const uint32_t Wb = (l & 1) ? (uint32_t)SM_A0 : (uint32_t)SM_A1;
            const float* bp = Bias[l];
            const int trow  = rowbase + (lane >> 2);
            const int tcol0 = wn * 64 + 2 * (lane & 3);
            #pragma unroll
            for (int mt = 0; mt < 2; mt++) {
                const int r0 = trow + mt * 16;
                const int r1 = r0 + 8;
                const float tv0 = tv[r0], tv1 = tv[r1];
                #pragma unroll
                for (int nt = 0; nt < 8; nt++) {
                    int col = tcol0 + nt * 8;
                    float2 bb = *(const float2*)(bp + col);
                    float a0 = acc[mt][nt][0], a1 = acc[mt][nt][1];
                    float a2 = acc[mt][nt][2], a3 = acc[mt][nt][3];
                    if (l == 0) {   // exact rank-1 t-term: tv * w0[576,:]
                        float wa = __ldg(w0_raw + 576 * 256 + col);
                        float wb = __ldg(w0_raw + 576 * 256 + col + 1);
                        a0 = fmaf(tv0, wa, a0); a1 = fmaf(tv0, wb, a1);
                        a2 = fmaf(tv1, wa, a2); a3 = fmaf(tv1, wb, a3);
                    }
                    float v00 = __sinf(W0F * (a0 + bb.x));
                    float v01 = __sinf(W0F * (a1 + bb.y));
                    float v10 = __sinf(W0F * (a2 + bb.x));
                    float v11 = __sinf(W0F * (a3 + bb.y));
                    uint32_t o0 = (uint32_t)((r0 * SA + col) * 2);
                    uint32_t o1 = (uint32_t)((r1 * SA + col) * 2);
                    *(__half2*)(smem + Wb + o0) =
                        __halves2half2(__float2half_rn(v00), __float2half_rn(v01));
                    *(__half2*)(smem + Wb + o1) =
                        __halves2half2(__float2half_rn(v10), __float2half_rn(v11));
                }
            }
        }
    }

    // ---------------- L4: 256 -> 27 via HMMA (16 warps, 16x16 tiles) ----------------
    {
        CP_WAIT0();                               // L4 B landed
        __syncthreads();                          // L3 epilogue (A0) + L4 B visible

        const int wm4 = w >> 1;                   // 0..7 : A rows 16*wm4
        const int wn4 = w & 1;                    // 0..1 : B n-base 16*wn4
        const uint32_t aHi4 = sb + SM_A0 +
            (uint32_t)(((wm4 * 16 + (lane & 15)) * SA + ((lane >> 4) << 3)) * 2);
        const uint32_t b_off4 = (uint32_t)(((wn4 * 16 + ((lane >> 4) << 3) + (lane & 7)) * SB4 +
                                           ((lane >> 3) & 1) * 8) * 2);
        const uint32_t bHi4 = sb + SM_BH0 + b_off4;
        const uint32_t bLo4 = sb + SM_BL0 + b_off4;

        float acc4[2][4];
        #pragma unroll
        for (int nt = 0; nt < 2; nt++)
            #pragma unroll
            for (int i = 0; i < 4; i++) acc4[nt][i] = 0.0f;

        #pragma unroll 4
        for (int ks = 0; ks < 16; ks++) {
            uint32_t Ah[4], Bh[4], Bl[4];
            LDSM4(Ah, aHi4 + (uint32_t)(ks * 32));
            LDSM4(Bh, bHi4 + (uint32_t)(ks * 32));
            mma_f32(acc4[0], Ah, Bh);
            mma_f32(acc4[1], Ah, Bh + 2);
            LDSM4(Bl, bLo4 + (uint32_t)(ks * 32));
            mma_f32(acc4[0], Ah, Bl);
            mma_f32(acc4[1], Ah, Bl + 2);
        }

        const int r0 = wm4 * 16 + (lane >> 2);
        const int r1 = r0 + 8;
        const int qg0 = qbase + r0, qg1 = qbase + r1;
        #pragma unroll
        for (int nt = 0; nt < 2; nt++) {
            int col = wn4 * 16 + nt * 8 + 2 * (lane & 3);
            if (col < 27) {
                float bv = __ldg(b4 + col);
                g_pat[qg0 * 27 + col] = acc4[nt][0] + bv;
                g_pat[qg1 * 27 + col] = acc4[nt][2] + bv;
            }
            if (col + 1 < 27) {
                float bv = __ldg(b4 + col + 1);
                g_pat[qg0 * 27 + col + 1] = acc4[nt][1] + bv;
                g_pat[qg1 * 27 + col + 1] = acc4[nt][3] + bv;
            }
        }
    }
}

// ---------------- fold3 ----------------
__global__ void fold_kernel(float* __restrict__ out) {
    int idx = blockIdx.x * blockDim.x + threadIdx.x;
    if (idx >= 2 * QN) return;
    int b = idx >> 16;
    int p = idx & (QN - 1);
    int y = p >> 8, x = p & 255;
    float s0 = 0.f, s1 = 0.f, s2 = 0.f;
    #pragma unroll
    for (int i = 0; i < 3; i++) {
        int yy = y + 1 - i;
        if (yy < 0 || yy >= HH) continue;
        #pragma unroll
        for (int j = 0; j < 3; j++) {
            int xx = x + 1 - j;
            if (xx < 0 || xx >= WWI) continue;
            const float* pp = g_pat + (b * QN + yy * WWI + xx) * 27 + i * 3 + j;
            s0 += pp[0];
            s1 += pp[9];
            s2 += pp[18];
        }
    }
    out[(b * 3 + 0) * QN + p] = s0;
    out[(b * 3 + 1) * QN + p] = s1;
    out[(b * 3 + 2) * QN + p] = s2;
}

extern "C" void kernel_launch(void* const* d_in, const int* in_sizes, int n_in,
                              void* d_out, int out_size) {
    const float* feat  = (const float*)d_in[0];
    const float* coord = (const float*)d_in[1];
    const float* w0 = (const float*)d_in[2];
    const float* b0 = (const float*)d_in[3];
    const float* w1 = (const float*)d_in[4];
    const float* b1 = (const float*)d_in[5];
    const float* w2 = (const float*)d_in[6];
    const float* b2 = (const float*)d_in[7];
    const float* w3 = (const float*)d_in[8];
    const float* b3 = (const float*)d_in[9];
    const float* w4 = (const float*)d_in[10];
    const float* b4 = (const float*)d_in[11];
    float* out = (float*)d_out;

    prep_kernel<<<(WT_ELEMS + 255) / 256, 256>>>(w0, w1, w2, w3, w4);

    cudaFuncSetAttribute(mlp_hmma, cudaFuncAttributeMaxDynamicSharedMemorySize, SM_TOTAL);
    mlp_hmma<<<(2 * QN) / MQ, 512, SM_TOTAL>>>(feat, coord, w0, b0, b1, b2, b3, b4);

    fold_kernel<<<(2 * QN + 255) / 256, 256>>>(out);
}

// round 16
// speedup vs baseline: 3.5644x; 1.0753x over previous
#include <cuda_runtime.h>
#include <cuda_fp16.h>
#include <cstdint>

// ============================================================
// LIIF_3d via HMMA. Precision plan (measured error budget):
//   L0 : 2-split weights (ah*bh + ah*bl)  — K=576, feeds everything
//   L1-3: single MMA ah*bh (weight-lo dropped; adds ~3.4e-4/layer, budgeted)
//   L4 : 2-split HMMA (effectively exact)
// k32 cp.async pipeline, one barrier per chunk, gather fully in-stream,
// epilogue ping-pong, L4 B staged in the last L3 chunk slot.
// MQ=128 queries/CTA, 512 threads, warp tile 32x64.
// L0 K=576 (t = exact fp32 rank-1). fold3 separate kernel.
// ============================================================

#define HH   256
#define WWI  256
#define QN   65536
#define CIN  64
#define W0F  30.0f
#define MQ   128
#define SA   264           // A row stride (halfs): 256 + 8 pad
#define SB   40            // B row stride (halfs): 32 + 8 pad (80B rows)
#define SB4  264           // L4 B row stride (halfs): 256 + 8 pad

#define SM_COORD 0                      // qy[128] qx[128] tv[128]
#define SM_A0    2048                   // A plane 0: 128*264*2 = 67584
#define SM_A1    69632                  // A plane 1
#define SM_BH0   137216                 // each B plane: 256*80 = 20480
#define SM_BL0   157696                 // (L4 B hi/lo reuse BH0/BL0: 32*528 each)
#define SM_BH1   178176
#define SM_BL1   198656
#define SM_TOTAL 219136                 // 214 KB

// transposed split weights [n][kp]: L0 256x640 (cols>=577 zero), L1-3 256x256,
// L4 32x256 (rows>=27 zero)
#define WT_ELEMS 368640
__device__ __align__(256) __half g_wt_hi[WT_ELEMS];
__device__ __align__(256) __half g_wt_lo[WT_ELEMS];
__device__ float  g_pat[2 * QN * 27];

static __device__ __forceinline__ uint32_t smem_u32(const void* p) {
    uint32_t a;
    asm("{ .reg .u64 t; cvta.to.shared.u64 t, %1; cvt.u32.u64 %0, t; }" : "=r"(a) : "l"(p));
    return a;
}

#define LDSM4(r, addr)                                                              \
    asm volatile("ldmatrix.sync.aligned.m8n8.x4.shared.b16 {%0,%1,%2,%3}, [%4];"    \
                 : "=r"((r)[0]), "=r"((r)[1]), "=r"((r)[2]), "=r"((r)[3])           \
                 : "r"(addr) : "memory")

#define CP16(dst, src) asm volatile("cp.async.cg.shared.global [%0], [%1], 16;" :: "r"(dst), "l"(src))
#define CP_COMMIT()    asm volatile("cp.async.commit_group;" ::: "memory")
#define CP_WAIT0()     asm volatile("cp.async.wait_group 0;" ::: "memory")

static __device__ __forceinline__ void mma_f32(float* c, const uint32_t* a, const uint32_t* b) {
    asm volatile(
        "mma.sync.aligned.m16n8k16.row.col.f32.f16.f16.f32 "
        "{%0,%1,%2,%3}, {%4,%5,%6,%7}, {%8,%9}, {%0,%1,%2,%3};"
        : "+f"(c[0]), "+f"(c[1]), "+f"(c[2]), "+f"(c[3])
        : "r"(a[0]), "r"(a[1]), "r"(a[2]), "r"(a[3]), "r"(b[0]), "r"(b[1]));
}

// ---------------- prep: transpose + hi/lo split ----------------
__global__ void prep_kernel(const float* __restrict__ w0, const float* __restrict__ w1,
                            const float* __restrict__ w2, const float* __restrict__ w3,
                            const float* __restrict__ w4) {
    int i = blockIdx.x * 256 + threadIdx.x;
    if (i >= WT_ELEMS) return;
    float v;
    if (i < 163840) {                 // L0 [256][640]
        int n = i / 640, k = i - n * 640;
        v = (k < 577) ? w0[k * 256 + n] : 0.0f;
    } else if (i < 229376) {
        int j = i - 163840; int n = j >> 8, k = j & 255; v = w1[k * 256 + n];
    } else if (i < 294912) {
        int j = i - 229376; int n = j >> 8, k = j & 255; v = w2[k * 256 + n];
    } else if (i < 360448) {
        int j = i - 294912; int n = j >> 8, k = j & 255; v = w3[k * 256 + n];
    } else {                          // L4 [32][256], rows >= 27 zero
        int j = i - 360448; int n = j >> 8, k = j & 255;
        v = (n < 27) ? w4[k * 27 + n] : 0.0f;
    }
    __half h = __float2half_rn(v);
    g_wt_hi[i] = h;
    g_wt_lo[i] = __float2half_rn(v - __half2float(h));
}

// stage one k32 chunk of B via cp.async; hi plane always, lo plane optionally
static __device__ __forceinline__ void stage_b(uint32_t bh, uint32_t bl,
                                               const __half* srcH, const __half* srcL,
                                               int kp, int kg, int tid, bool with_lo) {
    #pragma unroll
    for (int p = 0; p < 2; p++) {
        int idx = tid + p * 512;              // 0..1023 : n = idx>>2, u = idx&3
        int n = idx >> 2, u = idx & 3;
        CP16(bh + (uint32_t)(n * 80 + u * 16), srcH + n * kp + kg + u * 8);
        if (with_lo)
            CP16(bl + (uint32_t)(n * 80 + u * 16), srcL + n * kp + kg + u * 8);
    }
    CP_COMMIT();
}

// ---------------- fused MLP ----------------
__global__ __launch_bounds__(512, 1)
void mlp_hmma(const float* __restrict__ feat, const float* __restrict__ coord,
              const float* __restrict__ w0_raw,
              const float* __restrict__ b0, const float* __restrict__ b1,
              const float* __restrict__ b2, const float* __restrict__ b3,
              const float* __restrict__ b4) {
    extern __shared__ char smem[];
    const uint32_t sb = smem_u32(smem);
    int*   qy = (int*)(smem + SM_COORD);
    int*   qx = qy + MQ;
    float* tv = (float*)(qx + MQ);

    const int tid  = threadIdx.x;
    const int lane = tid & 31;
    const int w    = tid >> 5;
    const int wm   = w >> 2;           // 0..3 (M groups of 32 rows)
    const int wn   = w & 3;            // 0..3 (N groups of 64 cols)
    const int qbase = blockIdx.x * MQ;
    const int bimg  = qbase >> 16;

    if (tid < MQ) {
        int qg = qbase + tid;
        int q  = qg & (QN - 1);
        const float* cp = coord + (bimg * QN + q) * 3;
        float cy = cp[0], cx = cp[1];
        const float e = 1e-6f;
        cy = fminf(fmaxf(cy, -1.0f + e), 1.0f - e);
        cx = fminf(fmaxf(cx, -1.0f + e), 1.0f - e);
        int iy = (int)rintf((cy + 1.0f) * (HH * 0.5f) - 0.5f);
        int ix = (int)rintf((cx + 1.0f) * (WWI * 0.5f) - 0.5f);
        qy[tid] = min(max(iy, 0), HH - 1);
        qx[tid] = min(max(ix, 0), WWI - 1);
        tv[tid] = cp[2];
    }
    __syncthreads();

    auto gather_range = [&](int k0, int ncols, uint32_t ab) {
        for (int idx = tid; idx < MQ * ncols; idx += 512) {
            int q = idx & (MQ - 1);
            int k = k0 + (idx >> 7);           // < 576
            int ci = k / 9, r9 = k - ci * 9;
            int di = r9 / 3, dj = r9 - di * 3;
            int yy = qy[q] + di - 1, xx = qx[q] + dj - 1;
            float v = (yy >= 0 && yy < HH && xx >= 0 && xx < WWI)
                ? __ldg(feat + ((bimg * CIN + ci) * HH + yy) * WWI + xx) : 0.0f;
            *(__half*)(smem + ab + (uint32_t)((q * SA + (k & 255)) * 2)) = __float2half_rn(v);
        }
    };

    const float* Bias[4] = {b0, b1, b2, b3};
    const int seg[4] = {0, 163840, 229376, 294912};
    const int kps[4] = {640, 256, 256, 256};
    const int KL[4]  = {576, 256, 256, 256};

    const int rowbase = wm * 32;
    const uint32_t a_off = (uint32_t)(((rowbase + (lane & 15)) * SA + ((lane >> 4) << 3)) * 2);
    const uint32_t b_off = (uint32_t)(((wn * 64 + ((lane >> 4) << 3) + (lane & 7)) * SB +
                                      ((lane >> 3) & 1) * 8) * 2);
    const uint32_t BHp[2] = {sb + SM_BH0, sb + SM_BH1};
    const uint32_t BLp[2] = {sb + SM_BL0, sb + SM_BL1};

    // prefetch very first chunk (L0, kg=0, with lo) into buffer 0
    stage_b(BHp[0], BLp[0], g_wt_hi, g_wt_lo, 640, 0, tid, true);
    // exposed initial gather: cols 0..31 only
    gather_range(0, 32, SM_A0);

    float acc[2][8][4];
    int pb = 0;

    for (int l = 0; l < 4; l++) {
        #pragma unroll
        for (int mt = 0; mt < 2; mt++)
            #pragma unroll
            for (int nt = 0; nt < 8; nt++)
                #pragma unroll
                for (int i = 0; i < 4; i++) acc[mt][nt][i] = 0.0f;

        for (int kg = 0; kg < KL[l]; kg += 32) {
            CP_WAIT0();           // current chunk landed
            __syncthreads();      // publish chunk + gathered cols; prev readers done

            // prefetch next chunk in the GLOBAL sequence
            {
                int nl = l, nkg = kg + 32;
                if (nkg >= KL[l]) { nl = l + 1; nkg = 0; }
                if (nl < 4) {
                    stage_b(BHp[pb ^ 1], BLp[pb ^ 1],
                            g_wt_hi + seg[nl], g_wt_lo + seg[nl], kps[nl], nkg, tid,
                            nl == 0);
                } else {
                    // last chunk (l=3,kg=224): pb==1 -> buffer 0 free; stage L4 B hi/lo
                    #pragma unroll
                    for (int p = 0; p < 4; p++) {
                        int idx = tid + p * 512;          // 0..2047
                        int pl = idx >> 10;
                        int r  = idx & 1023;
                        int n = r >> 5, u = r & 31;
                        const __half* src = (pl ? g_wt_lo : g_wt_hi) + 360448 + n * 256 + u * 8;
                        uint32_t dst = (pl ? (sb + SM_BL0) : (sb + SM_BH0))
                                       + (uint32_t)(n * 528 + u * 16);
                        CP16(dst, src);
                    }
                    CP_COMMIT();
                }
            }

            const uint32_t Ab = (l == 0) ? (((kg >> 8) & 1) ? (uint32_t)SM_A1 : (uint32_t)SM_A0)
                                         : ((l & 1) ? (uint32_t)SM_A1 : (uint32_t)SM_A0);
            const uint32_t aHi = sb + Ab + a_off;
            const uint32_t bHi = BHp[pb] + b_off;
            const uint32_t bLo = BLp[pb] + b_off;

            #pragma unroll
            for (int ks = 0; ks < 2; ks++) {
                const uint32_t ca2 = (uint32_t)(((kg & 255) + ks * 16) * 2);
                uint32_t Ah[8];
                LDSM4(Ah,     aHi + ca2);
                LDSM4(Ah + 4, aHi + ca2 + 16 * SA * 2);
                {
                    uint32_t Bh[16];
                    #pragma unroll
                    for (int p = 0; p < 4; p++)
                        LDSM4(Bh + 4 * p, bHi + (uint32_t)(p * 16 * SB * 2 + ks * 32));
                    #pragma unroll
                    for (int mt = 0; mt < 2; mt++)
                        #pragma unroll
                        for (int nt = 0; nt < 8; nt++)
                            mma_f32(acc[mt][nt], Ah + 4 * mt, Bh + 2 * nt);
                }
                if (l == 0) {        // weight-lo correction only on L0
                    uint32_t Bl[16];
                    #pragma unroll
                    for (int p = 0; p < 4; p++)
                        LDSM4(Bl + 4 * p, bLo + (uint32_t)(p * 16 * SB * 2 + ks * 32));
                    #pragma unroll
                    for (int mt = 0; mt < 2; mt++)
                        #pragma unroll
                        for (int nt = 0; nt < 8; nt++)
                            mma_f32(acc[mt][nt], Ah + 4 * mt, Bl + 2 * nt);
                }
            }

            // interleaved gathers (L0 only)
            if (l == 0) {
                int c = kg >> 5;                    // 0..17
                if (kg < 256) {
                    if (c < 7) gather_range(32 * (c + 1), 32, SM_A0);
                    gather_range(256 + c * 32, 32, SM_A1);
                } else if (kg < 512) {
                    gather_range(512 + (c - 8) * 8, 8, SM_A0);
                }
            }

            pb ^= 1;
        }

        // ---- epilogue: no barrier; writes go to the OPPOSITE A buffer ----
        {
            const uint32_t Wb = (l & 1) ? (uint32_t)SM_A0 : (uint32_t)SM_A1;
            const float* bp = Bias[l];
            const int trow  = rowbase + (lane >> 2);
            const int tcol0 = wn * 64 + 2 * (lane & 3);
            #pragma unroll
            for (int mt = 0; mt < 2; mt++) {
                const int r0 = trow + mt * 16;
                const int r1 = r0 + 8;
                const float tv0 = tv[r0], tv1 = tv[r1];
                #pragma unroll
                for (int nt = 0; nt < 8; nt++) {
                    int col = tcol0 + nt * 8;
                    float2 bb = *(const float2*)(bp + col);
                    float a0 = acc[mt][nt][0], a1 = acc[mt][nt][1];
                    float a2 = acc[mt][nt][2], a3 = acc[mt][nt][3];
                    if (l == 0) {   // exact rank-1 t-term: tv * w0[576,:]
                        float wa = __ldg(w0_raw + 576 * 256 + col);
                        float wb = __ldg(w0_raw + 576 * 256 + col + 1);
                        a0 = fmaf(tv0, wa, a0); a1 = fmaf(tv0, wb, a1);
                        a2 = fmaf(tv1, wa, a2); a3 = fmaf(tv1, wb, a3);
                    }
                    float v00 = __sinf(W0F * (a0 + bb.x));
                    float v01 = __sinf(W0F * (a1 + bb.y));
                    float v10 = __sinf(W0F * (a2 + bb.x));
                    float v11 = __sinf(W0F * (a3 + bb.y));
                    uint32_t o0 = (uint32_t)((r0 * SA + col) * 2);
                    uint32_t o1 = (uint32_t)((r1 * SA + col) * 2);
                    *(__half2*)(smem + Wb + o0) =
                        __halves2half2(__float2half_rn(v00), __float2half_rn(v01));
                    *(__half2*)(smem + Wb + o1) =
                        __halves2half2(__float2half_rn(v10), __float2half_rn(v11));
                }
            }
        }
    }

    // ---------------- L4: 256 -> 27 via HMMA (16 warps, 16x16 tiles) ----------------
    {
        CP_WAIT0();                               // L4 B landed
        __syncthreads();                          // L3 epilogue (A0) + L4 B visible

        const int wm4 = w >> 1;                   // 0..7
        const int wn4 = w & 1;                    // 0..1
        const uint32_t aHi4 = sb + SM_A0 +
            (uint32_t)(((wm4 * 16 + (lane & 15)) * SA + ((lane >> 4) << 3)) * 2);
        const uint32_t b_off4 = (uint32_t)(((wn4 * 16 + ((lane >> 4) << 3) + (lane & 7)) * SB4 +
                                           ((lane >> 3) & 1) * 8) * 2);
        const uint32_t bHi4 = sb + SM_BH0 + b_off4;
        const uint32_t bLo4 = sb + SM_BL0 + b_off4;

        float acc4[2][4];
        #pragma unroll
        for (int nt = 0; nt < 2; nt++)
            #pragma unroll
            for (int i = 0; i < 4; i++) acc4[nt][i] = 0.0f;

        #pragma unroll 4
        for (int ks = 0; ks < 16; ks++) {
            uint32_t Ah[4], Bh[4], Bl[4];
            LDSM4(Ah, aHi4 + (uint32_t)(ks * 32));
            LDSM4(Bh, bHi4 + (uint32_t)(ks * 32));
            mma_f32(acc4[0], Ah, Bh);
            mma_f32(acc4[1], Ah, Bh + 2);
            LDSM4(Bl, bLo4 + (uint32_t)(ks * 32));
            mma_f32(acc4[0], Ah, Bl);
            mma_f32(acc4[1], Ah, Bl + 2);
        }

        const int r0 = wm4 * 16 + (lane >> 2);
        const int r1 = r0 + 8;
        const int qg0 = qbase + r0, qg1 = qbase + r1;
        #pragma unroll
        for (int nt = 0; nt < 2; nt++) {
            int col = wn4 * 16 + nt * 8 + 2 * (lane & 3);
            if (col < 27) {
                float bv = __ldg(b4 + col);
                g_pat[qg0 * 27 + col] = acc4[nt][0] + bv;
                g_pat[qg1 * 27 + col] = acc4[nt][2] + bv;
            }
            if (col + 1 < 27) {
                float bv = __ldg(b4 + col + 1);
                g_pat[qg0 * 27 + col + 1] = acc4[nt][1] + bv;
                g_pat[qg1 * 27 + col + 1] = acc4[nt][3] + bv;
            }
        }
    }
}

// ---------------- fold3 ----------------
__global__ void fold_kernel(float* __restrict__ out) {
    int idx = blockIdx.x * blockDim.x + threadIdx.x;
    if (idx >= 2 * QN) return;
    int b = idx >> 16;
    int p = idx & (QN - 1);
    int y = p >> 8, x = p & 255;
    float s0 = 0.f, s1 = 0.f, s2 = 0.f;
    #pragma unroll
    for (int i = 0; i < 3; i++) {
        int yy = y + 1 - i;
        if (yy < 0 || yy >= HH) continue;
        #pragma unroll
        for (int j = 0; j < 3; j++) {
            int xx = x + 1 - j;
            if (xx < 0 || xx >= WWI) continue;
            const float* pp = g_pat + (b * QN + yy * WWI + xx) * 27 + i * 3 + j;
            s0 += pp[0];
            s1 += pp[9];
            s2 += pp[18];
        }
    }
    out[(b * 3 + 0) * QN + p] = s0;
    out[(b * 3 + 1) * QN + p] = s1;
    out[(b * 3 + 2) * QN + p] = s2;
}

extern "C" void kernel_launch(void* const* d_in, const int* in_sizes, int n_in,
                              void* d_out, int out_size) {
    const float* feat  = (const float*)d_in[0];
    const float* coord = (const float*)d_in[1];
    const float* w0 = (const float*)d_in[2];
    const float* b0 = (const float*)d_in[3];
    const float* w1 = (const float*)d_in[4];
    const float* b1 = (const float*)d_in[5];
    const float* w2 = (const float*)d_in[6];
    const float* b2 = (const float*)d_in[7];
    const float* w3 = (const float*)d_in[8];
    const float* b3 = (const float*)d_in[9];
    const float* w4 = (const float*)d_in[10];
    const float* b4 = (const float*)d_in[11];
    float* out = (float*)d_out;

    prep_kernel<<<(WT_ELEMS + 255) / 256, 256>>>(w0, w1, w2, w3, w4);

    cudaFuncSetAttribute(mlp_hmma, cudaFuncAttributeMaxDynamicSharedMemorySize, SM_TOTAL);
    mlp_hmma<<<(2 * QN) / MQ, 512, SM_TOTAL>>>(feat, coord, w0, b0, b1, b2, b3, b4);

    fold_kernel<<<(2 * QN + 255) / 256, 256>>>(out);
}

// round 17
// speedup vs baseline: 4.2526x; 1.1931x over previous
#include <cuda_runtime.h>
#include <cuda_fp16.h>
#include <cstdint>

// ============================================================
// LIIF_3d via HMMA. Precision plan (measured):
//   L0 : 2-split weights (ah*bh + ah*bl), k32 chunks
//   L1-3: single MMA ah*bh, k64 chunks (hi plane only; lo not staged)
//   L4 : 2-split HMMA (effectively exact)
// k-chunk cp.async pipeline, one barrier per chunk, gather in-stream,
// epilogue ping-pong, L4 B staged in the last L3 chunk slot.
// MQ=128 queries/CTA, 512 threads, warp tile 32x64.
// L0 K=576 (t = exact fp32 rank-1). fold3 separate kernel.
// ============================================================

#define HH   256
#define WWI  256
#define QN   65536
#define CIN  64
#define W0F  30.0f
#define MQ   128
#define SA   264           // A row stride (halfs): 256 + 8 pad
#define SB   40            // L0 B row stride (halfs): 32 + 8 pad (80B rows)
#define SB2  72            // L1-3 B row stride (halfs): 64 + 8 pad (144B rows)
#define SB4  264           // L4 B row stride (halfs): 256 + 8 pad

#define SM_COORD 0                      // qy[128] qx[128] tv[128]
#define SM_A0    2048                   // A plane 0: 128*264*2 = 67584
#define SM_A1    69632                  // A plane 1
// B region 137216..219136 (81920B), two overlapping views:
//  L0 k32 hi/lo x2:  BH0 137216  BL0 157696  BH1 178176  BL1 198656 (20480 each)
//  L1-3 k64 hi x2:   BB0 137216  BB1 174080  (36864 each; BB1 ends 210944)
//  L4 hi||lo in BB0: hi 137216, lo 137216+16896 (ends 171008)
#define SM_BH0   137216
#define SM_BL0   157696
#define SM_BH1   178176
#define SM_BL1   198656
#define SM_BB0   137216
#define SM_BB1   174080
#define SM_TOTAL 219136                 // 214 KB

// transposed split weights [n][kp]: L0 256x640 (cols>=577 zero), L1-3 256x256,
// L4 32x256 (rows>=27 zero)
#define WT_ELEMS 368640
__device__ __align__(256) __half g_wt_hi[WT_ELEMS];
__device__ __align__(256) __half g_wt_lo[WT_ELEMS];
__device__ float  g_pat[2 * QN * 27];

static __device__ __forceinline__ uint32_t smem_u32(const void* p) {
    uint32_t a;
    asm("{ .reg .u64 t; cvta.to.shared.u64 t, %1; cvt.u32.u64 %0, t; }" : "=r"(a) : "l"(p));
    return a;
}

#define LDSM4(r, addr)                                                              \
    asm volatile("ldmatrix.sync.aligned.m8n8.x4.shared.b16 {%0,%1,%2,%3}, [%4];"    \
                 : "=r"((r)[0]), "=r"((r)[1]), "=r"((r)[2]), "=r"((r)[3])           \
                 : "r"(addr) : "memory")

#define CP16(dst, src) asm volatile("cp.async.cg.shared.global [%0], [%1], 16;" :: "r"(dst), "l"(src))
#define CP_COMMIT()    asm volatile("cp.async.commit_group;" ::: "memory")
#define CP_WAIT0()     asm volatile("cp.async.wait_group 0;" ::: "memory")

static __device__ __forceinline__ void mma_f32(float* c, const uint32_t* a, const uint32_t* b) {
    asm volatile(
        "mma.sync.aligned.m16n8k16.row.col.f32.f16.f16.f32 "
        "{%0,%1,%2,%3}, {%4,%5,%6,%7}, {%8,%9}, {%0,%1,%2,%3};"
        : "+f"(c[0]), "+f"(c[1]), "+f"(c[2]), "+f"(c[3])
        : "r"(a[0]), "r"(a[1]), "r"(a[2]), "r"(a[3]), "r"(b[0]), "r"(b[1]));
}

// ---------------- prep: transpose + hi/lo split ----------------
__global__ void prep_kernel(const float* __restrict__ w0, const float* __restrict__ w1,
                            const float* __restrict__ w2, const float* __restrict__ w3,
                            const float* __restrict__ w4) {
    int i = blockIdx.x * 256 + threadIdx.x;
    if (i >= WT_ELEMS) return;
    float v;
    if (i < 163840) {                 // L0 [256][640]
        int n = i / 640, k = i - n * 640;
        v = (k < 577) ? w0[k * 256 + n] : 0.0f;
    } else if (i < 229376) {
        int j = i - 163840; int n = j >> 8, k = j & 255; v = w1[k * 256 + n];
    } else if (i < 294912) {
        int j = i - 229376; int n = j >> 8, k = j & 255; v = w2[k * 256 + n];
    } else if (i < 360448) {
        int j = i - 294912; int n = j >> 8, k = j & 255; v = w3[k * 256 + n];
    } else {                          // L4 [32][256], rows >= 27 zero
        int j = i - 360448; int n = j >> 8, k = j & 255;
        v = (n < 27) ? w4[k * 27 + n] : 0.0f;
    }
    __half h = __float2half_rn(v);
    g_wt_hi[i] = h;
    g_wt_lo[i] = __float2half_rn(v - __half2float(h));
}

// stage one k32 chunk of L0 B (hi+lo) via cp.async
static __device__ __forceinline__ void stage_b32(uint32_t bh, uint32_t bl,
                                                 int kg, int tid) {
    #pragma unroll
    for (int p = 0; p < 2; p++) {
        int idx = tid + p * 512;              // 0..1023 : n = idx>>2, u = idx&3
        int n = idx >> 2, u = idx & 3;
        CP16(bh + (uint32_t)(n * 80 + u * 16), g_wt_hi + n * 640 + kg + u * 8);
        CP16(bl + (uint32_t)(n * 80 + u * 16), g_wt_lo + n * 640 + kg + u * 8);
    }
    CP_COMMIT();
}

// stage one k64 chunk of L1-3 B (hi only) via cp.async
static __device__ __forceinline__ void stage_b64(uint32_t bb, const __half* srcH,
                                                 int kg, int tid) {
    #pragma unroll
    for (int p = 0; p < 4; p++) {
        int idx = tid + p * 512;              // 0..2047 : n = idx>>3, u = idx&7
        int n = idx >> 3, u = idx & 7;
        CP16(bb + (uint32_t)(n * 144 + u * 16), srcH + n * 256 + kg + u * 8);
    }
    CP_COMMIT();
}

// ---------------- fused MLP ----------------
__global__ __launch_bounds__(512, 1)
void mlp_hmma(const float* __restrict__ feat, const float* __restrict__ coord,
              const float* __restrict__ w0_raw,
              const float* __restrict__ b0, const float* __restrict__ b1,
              const float* __restrict__ b2, const float* __restrict__ b3,
              const float* __restrict__ b4) {
    extern __shared__ char smem[];
    const uint32_t sb = smem_u32(smem);
    int*   qy = (int*)(smem + SM_COORD);
    int*   qx = qy + MQ;
    float* tv = (float*)(qx + MQ);

    const int tid  = threadIdx.x;
    const int lane = tid & 31;
    const int w    = tid >> 5;
    const int wm   = w >> 2;           // 0..3 (M groups of 32 rows)
    const int wn   = w & 3;            // 0..3 (N groups of 64 cols)
    const int qbase = blockIdx.x * MQ;
    const int bimg  = qbase >> 16;

    if (tid < MQ) {
        int qg = qbase + tid;
        int q  = qg & (QN - 1);
        const float* cp = coord + (bimg * QN + q) * 3;
        float cy = cp[0], cx = cp[1];
        const float e = 1e-6f;
        cy = fminf(fmaxf(cy, -1.0f + e), 1.0f - e);
        cx = fminf(fmaxf(cx, -1.0f + e), 1.0f - e);
        int iy = (int)rintf((cy + 1.0f) * (HH * 0.5f) - 0.5f);
        int ix = (int)rintf((cx + 1.0f) * (WWI * 0.5f) - 0.5f);
        qy[tid] = min(max(iy, 0), HH - 1);
        qx[tid] = min(max(ix, 0), WWI - 1);
        tv[tid] = cp[2];
    }
    __syncthreads();

    auto gather_range = [&](int k0, int ncols, uint32_t ab) {
        for (int idx = tid; idx < MQ * ncols; idx += 512) {
            int q = idx & (MQ - 1);
            int k = k0 + (idx >> 7);           // < 576
            int ci = k / 9, r9 = k - ci * 9;
            int di = r9 / 3, dj = r9 - di * 3;
            int yy = qy[q] + di - 1, xx = qx[q] + dj - 1;
            float v = (yy >= 0 && yy < HH && xx >= 0 && xx < WWI)
                ? __ldg(feat + ((bimg * CIN + ci) * HH + yy) * WWI + xx) : 0.0f;
            *(__half*)(smem + ab + (uint32_t)((q * SA + (k & 255)) * 2)) = __float2half_rn(v);
        }
    };

    const float* Bias[4] = {b0, b1, b2, b3};
    const int segh[4] = {0, 163840, 229376, 294912};

    const int rowbase = wm * 32;
    const uint32_t a_off = (uint32_t)(((rowbase + (lane & 15)) * SA + ((lane >> 4) << 3)) * 2);
    const uint32_t b_off32 = (uint32_t)(((wn * 64 + ((lane >> 4) << 3) + (lane & 7)) * SB +
                                        ((lane >> 3) & 1) * 8) * 2);
    const uint32_t b_off64 = (uint32_t)(((wn * 64 + ((lane >> 4) << 3) + (lane & 7)) * SB2 +
                                        ((lane >> 3) & 1) * 8) * 2);
    const uint32_t BHp[2] = {sb + SM_BH0, sb + SM_BH1};
    const uint32_t BLp[2] = {sb + SM_BL0, sb + SM_BL1};
    const uint32_t BB[2]  = {sb + SM_BB0, sb + SM_BB1};

    // prefetch very first chunk (L0, kg=0) into buffer 0
    stage_b32(BHp[0], BLp[0], 0, tid);
    // exposed initial gather: cols 0..31 only
    gather_range(0, 32, SM_A0);

    float acc[2][8][4];
    int pb = 0;

    // ===================== L0: K=576, k32 chunks, 2-split =====================
    #pragma unroll
    for (int mt = 0; mt < 2; mt++)
        #pragma unroll
        for (int nt = 0; nt < 8; nt++)
            #pragma unroll
            for (int i = 0; i < 4; i++) acc[mt][nt][i] = 0.0f;

    for (int kg = 0; kg < 576; kg += 32) {
        CP_WAIT0();
        __syncthreads();

        if (kg + 32 < 576)
            stage_b32(BHp[pb ^ 1], BLp[pb ^ 1], kg + 32, tid);
        else
            stage_b64(BB[0], g_wt_hi + segh[1], 0, tid);   // L1 chunk 0

        const uint32_t Ab = ((kg >> 8) & 1) ? (uint32_t)SM_A1 : (uint32_t)SM_A0;
        const uint32_t aHi = sb + Ab + a_off;
        const uint32_t bHi = BHp[pb] + b_off32;
        const uint32_t bLo = BLp[pb] + b_off32;

        #pragma unroll
        for (int ks = 0; ks < 2; ks++) {
            const uint32_t ca2 = (uint32_t)(((kg & 255) + ks * 16) * 2);
            uint32_t Ah[8];
            LDSM4(Ah,     aHi + ca2);
            LDSM4(Ah + 4, aHi + ca2 + 16 * SA * 2);
            {
                uint32_t Bh[16];
                #pragma unroll
                for (int p = 0; p < 4; p++)
                    LDSM4(Bh + 4 * p, bHi + (uint32_t)(p * 16 * SB * 2 + ks * 32));
                #pragma unroll
                for (int mt = 0; mt < 2; mt++)
                    #pragma unroll
                    for (int nt = 0; nt < 8; nt++)
                        mma_f32(acc[mt][nt], Ah + 4 * mt, Bh + 2 * nt);
            }
            {
                uint32_t Bl[16];
                #pragma unroll
                for (int p = 0; p < 4; p++)
                    LDSM4(Bl + 4 * p, bLo + (uint32_t)(p * 16 * SB * 2 + ks * 32));
                #pragma unroll
                for (int mt = 0; mt < 2; mt++)
                    #pragma unroll
                    for (int nt = 0; nt < 8; nt++)
                        mma_f32(acc[mt][nt], Ah + 4 * mt, Bl + 2 * nt);
            }
        }

        {   // interleaved gathers
            int c = kg >> 5;                    // 0..17
            if (kg < 256) {
                if (c < 7) gather_range(32 * (c + 1), 32, SM_A0);
                gather_range(256 + c * 32, 32, SM_A1);
            } else if (kg < 512) {
                gather_range(512 + (c - 8) * 8, 8, SM_A0);
            }
        }
        pb ^= 1;
    }

    // ---- L0 epilogue -> A1 (no barrier; A1 readers done at kg=512 barrier) ----
    {
        const float* bp = Bias[0];
        const int trow  = rowbase + (lane >> 2);
        const int tcol0 = wn * 64 + 2 * (lane & 3);
        #pragma unroll
        for (int mt = 0; mt < 2; mt++) {
            const int r0 = trow + mt * 16;
            const int r1 = r0 + 8;
            const float tv0 = tv[r0], tv1 = tv[r1];
            #pragma unroll
            for (int nt = 0; nt < 8; nt++) {
                int col = tcol0 + nt * 8;
                float2 bb = *(const float2*)(bp + col);
                float wa = __ldg(w0_raw + 576 * 256 + col);
                float wb = __ldg(w0_raw + 576 * 256 + col + 1);
                float a0 = fmaf(tv0, wa, acc[0 + mt][nt][0]);
                float a1 = fmaf(tv0, wb, acc[mt][nt][1]);
                float a2 = fmaf(tv1, wa, acc[mt][nt][2]);
                float a3 = fmaf(tv1, wb, acc[mt][nt][3]);
                float v00 = __sinf(W0F * (a0 + bb.x));
                float v01 = __sinf(W0F * (a1 + bb.y));
                float v10 = __sinf(W0F * (a2 + bb.x));
                float v11 = __sinf(W0F * (a3 + bb.y));
                uint32_t o0 = (uint32_t)((r0 * SA + col) * 2);
                uint32_t o1 = (uint32_t)((r1 * SA + col) * 2);
                *(__half2*)(smem + SM_A1 + o0) =
                    __halves2half2(__float2half_rn(v00), __float2half_rn(v01));
                *(__half2*)(smem + SM_A1 + o1) =
                    __halves2half2(__float2half_rn(v10), __float2half_rn(v11));
            }
        }
    }

    // ===================== L1-3: K=256, k64 chunks, hi only =====================
    int pb64 = 0;
    for (int l = 1; l < 4; l++) {
        #pragma unroll
        for (int mt = 0; mt < 2; mt++)
            #pragma unroll
            for (int nt = 0; nt < 8; nt++)
                #pragma unroll
                for (int i = 0; i < 4; i++) acc[mt][nt][i] = 0.0f;

        for (int kg = 0; kg < 256; kg += 64) {
            CP_WAIT0();
            __syncthreads();

            {
                int nl = l, nkg = kg + 64;
                if (nkg >= 256) { nl = l + 1; nkg = 0; }
                if (nl < 4) {
                    stage_b64(BB[pb64 ^ 1], g_wt_hi + segh[nl], nkg, tid);
                } else {
                    // last L3 chunk: pb64==1 -> BB0 free; stage L4 B hi||lo there
                    #pragma unroll
                    for (int p = 0; p < 4; p++) {
                        int idx = tid + p * 512;          // 0..2047
                        int pl = idx >> 10;
                        int r  = idx & 1023;
                        int n = r >> 5, u = r & 31;
                        const __half* src = (pl ? g_wt_lo : g_wt_hi) + 360448 + n * 256 + u * 8;
                        uint32_t dst = sb + SM_BB0 + (pl ? 16896u : 0u)
                                       + (uint32_t)(n * 528 + u * 16);
                        CP16(dst, src);
                    }
                    CP_COMMIT();
                }
            }

            const uint32_t aHi = sb + ((l & 1) ? (uint32_t)SM_A1 : (uint32_t)SM_A0) + a_off;
            const uint32_t bB  = BB[pb64] + b_off64;

            #pragma unroll
            for (int ks = 0; ks < 4; ks++) {
                const uint32_t ca2 = (uint32_t)((kg + ks * 16) * 2);
                uint32_t Ah[8];
                LDSM4(Ah,     aHi + ca2);
                LDSM4(Ah + 4, aHi + ca2 + 16 * SA * 2);
                uint32_t Bh[16];
                #pragma unroll
                for (int p = 0; p < 4; p++)
                    LDSM4(Bh + 4 * p, bB + (uint32_t)(p * 16 * SB2 * 2 + ks * 32));
                #pragma unroll
                for (int mt = 0; mt < 2; mt++)
                    #pragma unroll
                    for (int nt = 0; nt < 8; nt++)
                        mma_f32(acc[mt][nt], Ah + 4 * mt, Bh + 2 * nt);
            }
            pb64 ^= 1;
        }

        // ---- epilogue: writes the OPPOSITE A buffer (no barrier) ----
        {
            const uint32_t Wb = (l & 1) ? (uint32_t)SM_A0 : (uint32_t)SM_A1;
            const float* bp = Bias[l];
            const int trow  = rowbase + (lane >> 2);
            const int tcol0 = wn * 64 + 2 * (lane & 3);
            #pragma unroll
            for (int mt = 0; mt < 2; mt++) {
                const int r0 = trow + mt * 16;
                const int r1 = r0 + 8;
                #pragma unroll
                for (int nt = 0; nt < 8; nt++) {
                    int col = tcol0 + nt * 8;
                    float2 bb = *(const float2*)(bp + col);
                    float v00 = __sinf(W0F * (acc[mt][nt][0] + bb.x));
                    float v01 = __sinf(W0F * (acc[mt][nt][1] + bb.y));
                    float v10 = __sinf(W0F * (acc[mt][nt][2] + bb.x));
                    float v11 = __sinf(W0F * (acc[mt][nt][3] + bb.y));
                    uint32_t o0 = (uint32_t)((r0 * SA + col) * 2);
                    uint32_t o1 = (uint32_t)((r1 * SA + col) * 2);
                    *(__half2*)(smem + Wb + o0) =
                        __halves2half2(__float2half_rn(v00), __float2half_rn(v01));
                    *(__half2*)(smem + Wb + o1) =
                        __halves2half2(__float2half_rn(v10), __float2half_rn(v11));
                }
            }
        }
    }

    // ---------------- L4: 256 -> 27 via HMMA (16 warps, 16x16 tiles) ----------------
    {
        CP_WAIT0();                               // L4 B landed
        __syncthreads();                          // L3 epilogue (A0) + L4 B visible

        const int wm4 = w >> 1;                   // 0..7
        const int wn4 = w & 1;                    // 0..1
        const uint32_t aHi4 = sb + SM_A0 +
            (uint32_t)(((wm4 * 16 + (lane & 15)) * SA + ((lane >> 4) << 3)) * 2);
        const uint32_t b_off4 = (uint32_t)(((wn4 * 16 + ((lane >> 4) << 3) + (lane & 7)) * SB4 +
                                           ((lane >> 3) & 1) * 8) * 2);
        const uint32_t bHi4 = sb + SM_BB0 + b_off4;
        const uint32_t bLo4 = sb + SM_BB0 + 16896u + b_off4;

        float acc4[2][4];
        #pragma unroll
        for (int nt = 0; nt < 2; nt++)
            #pragma unroll
            for (int i = 0; i < 4; i++) acc4[nt][i] = 0.0f;

        #pragma unroll 4
        for (int ks = 0; ks < 16; ks++) {
            uint32_t Ah[4], Bh[4], Bl[4];
            LDSM4(Ah, aHi4 + (uint32_t)(ks * 32));
            LDSM4(Bh, bHi4 + (uint32_t)(ks * 32));
            mma_f32(acc4[0], Ah, Bh);
            mma_f32(acc4[1], Ah, Bh + 2);
            LDSM4(Bl, bLo4 + (uint32_t)(ks * 32));
            mma_f32(acc4[0], Ah, Bl);
            mma_f32(acc4[1], Ah, Bl + 2);
        }

        const int r0 = wm4 * 16 + (lane >> 2);
        const int r1 = r0 + 8;
        const int qg0 = qbase + r0, qg1 = qbase + r1;
        #pragma unroll
        for (int nt = 0; nt < 2; nt++) {
            int col = wn4 * 16 + nt * 8 + 2 * (lane & 3);
            if (col < 27) {
                float bv = __ldg(b4 + col);
                g_pat[qg0 * 27 + col] = acc4[nt][0] + bv;
                g_pat[qg1 * 27 + col] = acc4[nt][2] + bv;
            }
            if (col + 1 < 27) {
                float bv = __ldg(b4 + col + 1);
                g_pat[qg0 * 27 + col + 1] = acc4[nt][1] + bv;
                g_pat[qg1 * 27 + col + 1] = acc4[nt][3] + bv;
            }
        }
    }
}

// ---------------- fold3 ----------------
__global__ void fold_kernel(float* __restrict__ out) {
    int idx = blockIdx.x * blockDim.x + threadIdx.x;
    if (idx >= 2 * QN) return;
    int b = idx >> 16;
    int p = idx & (QN - 1);
    int y = p >> 8, x = p & 255;
    float s0 = 0.f, s1 = 0.f, s2 = 0.f;
    #pragma unroll
    for (int i = 0; i < 3; i++) {
        int yy = y + 1 - i;
        if (yy < 0 || yy >= HH) continue;
        #pragma unroll
        for (int j = 0; j < 3; j++) {
            int xx = x + 1 - j;
            if (xx < 0 || xx >= WWI) continue;
            const float* pp = g_pat + (b * QN + yy * WWI + xx) * 27 + i * 3 + j;
            s0 += pp[0];
            s1 += pp[9];
            s2 += pp[18];
        }
    }
    out[(b * 3 + 0) * QN + p] = s0;
    out[(b * 3 + 1) * QN + p] = s1;
    out[(b * 3 + 2) * QN + p] = s2;
}

extern "C" void kernel_launch(void* const* d_in, const int* in_sizes, int n_in,
                              void* d_out, int out_size) {
    const float* feat  = (const float*)d_in[0];
    const float* coord = (const float*)d_in[1];
    const float* w0 = (const float*)d_in[2];
    const float* b0 = (const float*)d_in[3];
    const float* w1 = (const float*)d_in[4];
    const float* b1 = (const float*)d_in[5];
    const float* w2 = (const float*)d_in[6];
    const float* b2 = (const float*)d_in[7];
    const float* w3 = (const float*)d_in[8];
    const float* b3 = (const float*)d_in[9];
    const float* w4 = (const float*)d_in[10];
    const float* b4 = (const float*)d_in[11];
    float* out = (float*)d_out;

    prep_kernel<<<(WT_ELEMS + 255) / 256, 256>>>(w0, w1, w2, w3, w4);

    cudaFuncSetAttribute(mlp_hmma, cudaFuncAttributeMaxDynamicSharedMemorySize, SM_TOTAL);
    mlp_hmma<<<(2 * QN) / MQ, 512, SM_TOTAL>>>(feat, coord, w0, b0, b1, b2, b3, b4);

    fold_kernel<<<(2 * QN + 255) / 256, 256>>>(out);
}